// round 5
// baseline (speedup 1.0000x reference)
#include <cuda_runtime.h>
#include <math.h>

#define B_  4
#define L_  4096
#define D_  192
#define EPSF 1e-5f

typedef unsigned long long ull;

__device__ float g_xm[B_*L_*D_];
__device__ float g_z [B_*L_*D_];
__device__ float g_xc[B_*L_*D_];
__device__ float g_dt[16*L_*D_];
__device__ float g_Bs[16*L_*16];
__device__ float g_Cs[16*L_*16];
__device__ float g_ys[16*L_*D_];
__device__ float g_hloc[16*64*16*D_];
__device__ float g_hin [16*64*16*D_];
__device__ float g_Tc[16*64*D_];

__device__ __forceinline__ int map_l(int k, int l) {
    if (k == 0) return l;
    if (k == 1) return ((l & 63) << 6) | (l >> 6);
    if (k == 2) return 4095 - l;
    int r = 4095 - l;
    return ((r & 63) << 6) | (r >> 6);
}

__device__ __forceinline__ ull pk(float lo, float hi) {
    ull r; asm("mov.b64 %0, {%1, %2};" : "=l"(r) : "f"(lo), "f"(hi)); return r;
}
__device__ __forceinline__ void upk(ull v, float& lo, float& hi) {
    asm("mov.b64 {%0, %1}, %2;" : "=f"(lo), "=f"(hi) : "l"(v));
}
__device__ __forceinline__ ull ffma2(ull a, ull b, ull c) {
    ull d; asm("fma.rn.f32x2 %0, %1, %2, %3;" : "=l"(d) : "l"(a), "l"(b), "l"(c)); return d;
}
__device__ __forceinline__ ull mul2(ull a, ull b) {
    ull d; asm("mul.rn.f32x2 %0, %1, %2;" : "=l"(d) : "l"(a), "l"(b)); return d;
}

// ================= Kernel 1: pre-chain =================
// pixel buffers stride 36, weight buffer stride 97 ([o][c], no transpose)
__global__ void __launch_bounds__(256) k_pre(
    const float* __restrict__ xd, const float* __restrict__ xsh,
    const float* __restrict__ w1, const float* __restrict__ b1,
    const float* __restrict__ ln1w, const float* __restrict__ ln1b,
    const float* __restrict__ w2, const float* __restrict__ b2,
    const float* __restrict__ ln2w, const float* __restrict__ ln2b,
    const float* __restrict__ nw, const float* __restrict__ nb,
    const float* __restrict__ wip)
{
    extern __shared__ float sm[];
    float* sW   = sm;              // 96*97 = 9312
    float* sA   = sW + 9312;       // 96*36 = 3456
    float* sB   = sA + 3456;       // 3456
    float* red  = sB + 3456;       // 256
    float* stat = red + 256;       // 64

    const int tid = threadIdx.x;
    const int lane = tid & 31;
    const int wp = tid >> 5;       // 0..7
    const int p0 = wp * 4;         // pixel quad base
    const int b  = blockIdx.x >> 7;
    const int l0 = (blockIdx.x & 127) << 5;

    auto loadW = [&](const float* W) {
        for (int idx = tid; idx < 96*96; idx += 256) {
            int o = idx / 96, c = idx % 96;
            sW[o*97 + c] = W[idx];      // consecutive c -> conflict-free writes
        }
    };

    auto gemm96 = [&](const float* in, float* out, const float* bias) {
        float a0[4] = {0,0,0,0}, a1[4] = {0,0,0,0}, a2[4] = {0,0,0,0};
        const float* w0p = &sW[lane*97];
        const float* w1p = &sW[(lane+32)*97];
        const float* w2p = &sW[(lane+64)*97];
        #pragma unroll 4
        for (int c = 0; c < 96; c++) {
            float4 xv = *(const float4*)&in[c*36 + p0];   // broadcast within warp
            float wv0 = w0p[c], wv1 = w1p[c], wv2 = w2p[c]; // bank=(lane+c)%32, conflict-free
            a0[0] = fmaf(wv0, xv.x, a0[0]); a0[1] = fmaf(wv0, xv.y, a0[1]);
            a0[2] = fmaf(wv0, xv.z, a0[2]); a0[3] = fmaf(wv0, xv.w, a0[3]);
            a1[0] = fmaf(wv1, xv.x, a1[0]); a1[1] = fmaf(wv1, xv.y, a1[1]);
            a1[2] = fmaf(wv1, xv.z, a1[2]); a1[3] = fmaf(wv1, xv.w, a1[3]);
            a2[0] = fmaf(wv2, xv.x, a2[0]); a2[1] = fmaf(wv2, xv.y, a2[1]);
            a2[2] = fmaf(wv2, xv.z, a2[2]); a2[3] = fmaf(wv2, xv.w, a2[3]);
        }
        float bv0 = bias ? bias[lane]    : 0.f;
        float bv1 = bias ? bias[lane+32] : 0.f;
        float bv2 = bias ? bias[lane+64] : 0.f;
        #pragma unroll
        for (int p = 0; p < 4; p++) {
            out[lane*36      + p0 + p] = a0[p] + bv0;
            out[(lane+32)*36 + p0 + p] = a1[p] + bv1;
            out[(lane+64)*36 + p0 + p] = a2[p] + bv2;
        }
    };

    auto lnorm = [&](float* buf, const float* w, const float* bi, bool dogelu) {
        int g = tid >> 5, li = tid & 31;
        float p = 0.f;
        #pragma unroll
        for (int j = 0; j < 12; j++) p += buf[(g + 8*j)*36 + li];
        red[g*32 + li] = p;
        __syncthreads();
        if (tid < 32) {
            float s = 0.f;
            #pragma unroll
            for (int g2 = 0; g2 < 8; g2++) s += red[g2*32 + tid];
            stat[tid] = s * (1.f/96.f);
        }
        __syncthreads();
        float m = stat[li];
        p = 0.f;
        #pragma unroll
        for (int j = 0; j < 12; j++) { float v = buf[(g + 8*j)*36 + li] - m; p = fmaf(v, v, p); }
        red[g*32 + li] = p;
        __syncthreads();
        if (tid < 32) {
            float s = 0.f;
            #pragma unroll
            for (int g2 = 0; g2 < 8; g2++) s += red[g2*32 + tid];
            stat[32 + tid] = rsqrtf(s * (1.f/96.f) + EPSF);
        }
        __syncthreads();
        #pragma unroll
        for (int j = 0; j < 12; j++) {
            int o = g + 8*j;
            float v = buf[o*36 + li];
            v = (v - stat[li]) * stat[32 + li] * w[o] + bi[o];
            if (dogelu) v = 0.5f * v * (1.f + erff(v * 0.70710678118f));
            buf[o*36 + li] = v;
        }
        __syncthreads();
    };

    for (int idx = tid; idx < 96*32; idx += 256) {
        int c = idx >> 5, li = idx & 31;
        int g = (b*96 + c)*4096 + l0 + li;
        sA[c*36 + li] = xd[g] + xsh[g];
    }
    loadW(w1);
    __syncthreads();
    gemm96(sA, sB, b1);
    __syncthreads();
    lnorm(sB, ln1w, ln1b, true);
    loadW(w2);
    __syncthreads();
    gemm96(sB, sA, b2);
    __syncthreads();
    lnorm(sA, ln2w, ln2b, false);
    lnorm(sA, nw, nb, false);
    for (int ch = 0; ch < 4; ch++) {
        loadW(wip + ch*96*96);
        __syncthreads();
        gemm96(sA, sB, nullptr);
        __syncthreads();
        float* dst = (ch < 2) ? g_xm : g_z;
        int dbase = (ch & 1) * 96;
        for (int idx = tid; idx < 96*32; idx += 256) {
            int li = idx / 96, dd = idx % 96;
            dst[(b*4096 + l0 + li)*192 + dbase + dd] = sB[dd*36 + li];
        }
        __syncthreads();
    }
}

// ================= Kernel 2: depthwise 3x3 + silu =================
__global__ void __launch_bounds__(256) k_dw(const float* __restrict__ cw, const float* __restrict__ cb)
{
    int idx = blockIdx.x * 256 + threadIdx.x;
    int d = idx % 192;
    int l = (idx / 192) & 4095;
    int b = idx / (192 * 4096);
    int h = l >> 6, w = l & 63;
    float acc = cb[d];
    #pragma unroll
    for (int dh = -1; dh <= 1; dh++) {
        int hh = h + dh;
        if ((unsigned)hh >= 64u) continue;
        #pragma unroll
        for (int dw = -1; dw <= 1; dw++) {
            int ww = w + dw;
            if ((unsigned)ww >= 64u) continue;
            acc = fmaf(g_xm[((b*4096) + (hh<<6) + ww)*192 + d],
                       cw[d*9 + (dh+1)*3 + (dw+1)], acc);
        }
    }
    g_xc[idx] = acc / (1.f + __expf(-acc));
}

// ================= Kernel 3: x_proj + dt proj + softplus (R2 version) =================
__global__ void __launch_bounds__(256) k_proj(
    const float* __restrict__ xpw, const float* __restrict__ dtw, const float* __restrict__ dtb)
{
    extern __shared__ float sm[];
    float* sX   = sm;               // 192*33
    float* sWp  = sX + 192*33;      // 192*40
    float* sDb  = sWp + 192*40;     // 38*33
    float* sdtw = sDb + 38*33;      // 1152
    float* sdtb = sdtw + 1152;      // 192
    float* sDt  = sdtb + 192;       // 192*33
    int tid = threadIdx.x;
    int bk = blockIdx.x >> 7;
    int tile = blockIdx.x & 127;
    int b = bk >> 2, k = bk & 3;
    int l0 = tile << 5;

    for (int idx = tid; idx < 192*32; idx += 256) {
        int li = idx / 192, d = idx % 192;
        int ml = map_l(k, l0 + li);
        sX[d*33 + li] = g_xc[(b*4096 + ml)*192 + d];
    }
    for (int idx = tid; idx < 38*192; idx += 256) {
        int c = idx / 192, d = idx % 192;
        sWp[d*40 + c] = xpw[(k*38 + c)*192 + d];
    }
    for (int idx = tid; idx < 1152; idx += 256) sdtw[idx] = dtw[k*1152 + idx];
    for (int idx = tid; idx < 192; idx += 256) sdtb[idx] = dtb[k*192 + idx];
    __syncthreads();
    {
        int og = tid >> 5, li = tid & 31;
        float acc[5] = {0.f,0.f,0.f,0.f,0.f};
        for (int d = 0; d < 192; d++) {
            float xv = sX[d*33 + li];
            #pragma unroll
            for (int j = 0; j < 5; j++) {
                int o = og + 8*j;
                if (o < 38) acc[j] = fmaf(sWp[d*40 + o], xv, acc[j]);
            }
        }
        #pragma unroll
        for (int j = 0; j < 5; j++) {
            int o = og + 8*j;
            if (o < 38) sDb[o*33 + li] = acc[j];
        }
    }
    __syncthreads();
    {
        int og = tid >> 5, li = tid & 31;
        float xr[6];
        #pragma unroll
        for (int r = 0; r < 6; r++) xr[r] = sDb[r*33 + li];
        #pragma unroll
        for (int j = 0; j < 24; j++) {
            int dd = og + 8*j;
            float acc = sdtb[dd];
            #pragma unroll
            for (int r = 0; r < 6; r++) acc = fmaf(xr[r], sdtw[dd*6 + r], acc);
            acc = (acc > 20.f) ? acc : log1pf(__expf(acc));
            sDt[dd*33 + li] = acc;
        }
    }
    __syncthreads();
    for (int idx = tid; idx < 192*32; idx += 256) {
        int li = idx / 192, dd = idx % 192;
        g_dt[((bk<<12) + l0 + li)*192 + dd] = sDt[dd*33 + li];
    }
    for (int idx = tid; idx < 32*16; idx += 256) {
        int li = idx >> 4, n = idx & 15;
        g_Bs[((bk<<12) + l0 + li)*16 + n] = sDb[(6 + n)*33 + li];
        g_Cs[((bk<<12) + l0 + li)*16 + n] = sDb[(22 + n)*33 + li];
    }
}

__device__ __forceinline__ void scan_maps(int k, int l0, int& ml0, int& mst) {
    if (k == 0)      { ml0 = l0;                          mst = 1;   }
    else if (k == 1) { ml0 = l0 >> 6;                     mst = 64;  }
    else if (k == 2) { ml0 = 4095 - l0;                   mst = -1;  }
    else             { ml0 = 4032 + 63 - (l0 >> 6);       mst = -64; }
}

// ================= Scan phase 1: chunk-local (R3 version: 192 thr, 16 states) =================
__global__ void __launch_bounds__(192) k_scan1(const float* __restrict__ Alogs)
{
    __shared__ float sB[1024];
    int d = threadIdx.x;
    int ch = blockIdx.x & 63;
    int bk = blockIdx.x >> 6;
    int b = bk >> 2, k = bk & 3;
    for (int idx = d; idx < 1024; idx += 192)
        sB[idx] = g_Bs[((bk<<12) + (ch<<6))*16 + idx];
    float Af[16]; bool stdA = true;
    #pragma unroll
    for (int n = 0; n < 16; n++) {
        Af[n] = -__expf(Alogs[(k*192 + d)*16 + n]);
        stdA = stdA && (fabsf(Af[n] + (float)(n+1)) < 1e-3f);
    }
    __syncthreads();
    int l0 = ch << 6;
    int ml0, mst;
    scan_maps(k, l0, ml0, mst);
    const float* dtp = g_dt + (((size_t)bk<<12) + l0)*192 + d;
    const float* xq  = g_xc + (((size_t)b<<12) + ml0)*192 + d;
    int xstep = mst * 192;
    float Ts = 0.f;
    int base = ((bk*64 + ch)*16)*192 + d;
    if (stdA) {
        ull H[8];
        #pragma unroll
        for (int i = 0; i < 8; i++) H[i] = 0;
        float dt_c = dtp[0], x_c = xq[0];
        #pragma unroll 2
        for (int s = 0; s < 64; s++) {
            float dt = dt_c, x = x_c;
            if (s < 63) { dt_c = dtp[(s+1)*192]; x_c = xq[(s+1)*xstep]; }
            float r = __expf(-dt);
            float dtx = dt * x;
            Ts += dt;
            float r2 = r * r;
            ull r2s = pk(r2, r2);
            ull P = pk(r, r2);
            ull dtxs = pk(dtx, dtx);
            const ull* Bp = (const ull*)(sB + s*16);
            H[0] = ffma2(P, H[0], mul2(dtxs, Bp[0]));
            #pragma unroll
            for (int i = 1; i < 8; i++) {
                P = mul2(P, r2s);
                H[i] = ffma2(P, H[i], mul2(dtxs, Bp[i]));
            }
        }
        #pragma unroll
        for (int i = 0; i < 8; i++) {
            float v0, v1;
            upk(H[i], v0, v1);
            g_hloc[base + (2*i)*192]   = v0;
            g_hloc[base + (2*i+1)*192] = v1;
        }
    } else {
        float h[16];
        #pragma unroll
        for (int n = 0; n < 16; n++) h[n] = 0.f;
        for (int s = 0; s < 64; s++) {
            float dt = dtp[s*192];
            float x  = xq[s*xstep];
            float dtx = dt * x;
            Ts += dt;
            const float* Bp = &sB[s*16];
            #pragma unroll
            for (int n = 0; n < 16; n++)
                h[n] = fmaf(__expf(dt * Af[n]), h[n], dtx * Bp[n]);
        }
        #pragma unroll
        for (int n = 0; n < 16; n++) g_hloc[base + n*192] = h[n];
    }
    g_Tc[(bk*64 + ch)*192 + d] = Ts;
}

// ================= Scan phase 2: chunk prefix =================
__global__ void k_scan_mid(const float* __restrict__ Alogs)
{
    int gid = blockIdx.x * 256 + threadIdx.x;
    int d = gid % 192;
    int n = (gid / 192) & 15;
    int bk = gid / (192*16);
    int k = bk & 3;
    float An = -__expf(Alogs[(k*192 + d)*16 + n]);
    float h = 0.f;
    int idx = (bk*64*16 + n)*192 + d;
    int tcb = bk*64*192 + d;
    float Tc_c = g_Tc[tcb];
    float hl_c = g_hloc[idx];
    for (int ch = 0; ch < 64; ch++) {
        float Tc = Tc_c, hl = hl_c;
        if (ch < 63) {
            Tc_c = g_Tc[tcb + (ch+1)*192];
            hl_c = g_hloc[idx + (ch+1)*16*192];
        }
        g_hin[idx + ch*16*192] = h;
        h = fmaf(__expf(An * Tc), h, hl);
    }
}

// ================= Scan phase 3: rescan + y (R3 version) =================
__global__ void __launch_bounds__(192) k_scan2(const float* __restrict__ Alogs, const float* __restrict__ Ds)
{
    __shared__ float sB[1024], sC[1024];
    int d = threadIdx.x;
    int ch = blockIdx.x & 63;
    int bk = blockIdx.x >> 6;
    int b = bk >> 2, k = bk & 3;
    for (int idx = d; idx < 1024; idx += 192) {
        sB[idx] = g_Bs[((bk<<12) + (ch<<6))*16 + idx];
        sC[idx] = g_Cs[((bk<<12) + (ch<<6))*16 + idx];
    }
    float Af[16]; bool stdA = true;
    #pragma unroll
    for (int n = 0; n < 16; n++) {
        Af[n] = -__expf(Alogs[(k*192 + d)*16 + n]);
        stdA = stdA && (fabsf(Af[n] + (float)(n+1)) < 1e-3f);
    }
    int base = ((bk*64 + ch)*16)*192 + d;
    float Dv = Ds[k*192 + d];
    __syncthreads();
    int l0 = ch << 6;
    int ml0, mst;
    scan_maps(k, l0, ml0, mst);
    const float* dtp = g_dt + (((size_t)bk<<12) + l0)*192 + d;
    const float* xq  = g_xc + (((size_t)b<<12) + ml0)*192 + d;
    int xstep = mst * 192;
    float* yp = g_ys + (((size_t)bk<<12) + l0)*192 + d;
    if (stdA) {
        ull H[8];
        #pragma unroll
        for (int i = 0; i < 8; i++)
            H[i] = pk(g_hin[base + (2*i)*192], g_hin[base + (2*i+1)*192]);
        float dt_c = dtp[0], x_c = xq[0];
        #pragma unroll 2
        for (int s = 0; s < 64; s++) {
            float dt = dt_c, x = x_c;
            if (s < 63) { dt_c = dtp[(s+1)*192]; x_c = xq[(s+1)*xstep]; }
            float r = __expf(-dt);
            float dtx = dt * x;
            float r2 = r * r;
            ull r2s = pk(r2, r2);
            ull P = pk(r, r2);
            ull dtxs = pk(dtx, dtx);
            ull Y = pk(Dv * x, 0.f);
            const ull* Bp = (const ull*)(sB + s*16);
            const ull* Cp = (const ull*)(sC + s*16);
            H[0] = ffma2(P, H[0], mul2(dtxs, Bp[0]));
            Y = ffma2(H[0], Cp[0], Y);
            #pragma unroll
            for (int i = 1; i < 8; i++) {
                P = mul2(P, r2s);
                H[i] = ffma2(P, H[i], mul2(dtxs, Bp[i]));
                Y = ffma2(H[i], Cp[i], Y);
            }
            float y0, y1;
            upk(Y, y0, y1);
            yp[s*192] = y0 + y1;
        }
    } else {
        float h[16];
        #pragma unroll
        for (int n = 0; n < 16; n++) h[n] = g_hin[base + n*192];
        for (int s = 0; s < 64; s++) {
            float dt = dtp[s*192];
            float x  = xq[s*xstep];
            float dtx = dt * x;
            float y = Dv * x;
            const float* Bp = &sB[s*16];
            const float* Cp = &sC[s*16];
            #pragma unroll
            for (int n = 0; n < 16; n++) {
                h[n] = fmaf(__expf(dt * Af[n]), h[n], dtx * Bp[n]);
                y = fmaf(h[n], Cp[n], y);
            }
            yp[s*192] = y;
        }
    }
}

// ================= Kernel 7: combine + out_norm + gate + out_proj + residual =================
// weights stride 193 ([c_out][dd], no transpose), pixel buffers stride 36
__global__ void __launch_bounds__(256) k_comb(
    const float* __restrict__ xd, const float* __restrict__ xsh,
    const float* __restrict__ onw, const float* __restrict__ onb,
    const float* __restrict__ opw, float* __restrict__ out)
{
    extern __shared__ float sm[];
    float* sW   = sm;              // 96*193 = 18528
    float* sY   = sW + 18528;      // 192*36 = 6912
    float* sO   = sY + 6912;       // 96*36 = 3456
    float* red  = sO + 3456;       // 256
    float* stat = red + 256;       // 64
    int tid = threadIdx.x;
    int lane = tid & 31;
    int wp = tid >> 5;
    int p0 = wp * 4;
    int b = blockIdx.x >> 7;
    int l0 = (blockIdx.x & 127) << 5;

    for (int idx = tid; idx < 96*192; idx += 256) {
        int c = idx / 192, dd = idx % 192;
        sW[c*193 + dd] = opw[idx];
    }
    for (int idx = tid; idx < 192*32; idx += 256) {
        int li = idx / 192, dd = idx % 192;
        int p = l0 + li;
        float acc = 0.f;
        #pragma unroll
        for (int k = 0; k < 4; k++) {
            int s = map_l(k, p);
            acc += g_ys[(((b*4 + k)<<12) + s)*192 + dd];
        }
        sY[dd*36 + li] = acc;
    }
    __syncthreads();
    {   // LN over 192 channels
        int g = tid >> 5, li = tid & 31;
        float p = 0.f;
        #pragma unroll
        for (int j = 0; j < 24; j++) p += sY[(g + 8*j)*36 + li];
        red[g*32 + li] = p;
        __syncthreads();
        if (tid < 32) {
            float s = 0.f;
            #pragma unroll
            for (int g2 = 0; g2 < 8; g2++) s += red[g2*32 + tid];
            stat[tid] = s * (1.f/192.f);
        }
        __syncthreads();
        float m = stat[li];
        p = 0.f;
        #pragma unroll
        for (int j = 0; j < 24; j++) { float v = sY[(g + 8*j)*36 + li] - m; p = fmaf(v, v, p); }
        red[g*32 + li] = p;
        __syncthreads();
        if (tid < 32) {
            float s = 0.f;
            #pragma unroll
            for (int g2 = 0; g2 < 8; g2++) s += red[g2*32 + tid];
            stat[32 + tid] = rsqrtf(s * (1.f/192.f) + EPSF);
        }
        __syncthreads();
    }
    {
        int g = tid >> 5, li = tid & 31;
        #pragma unroll
        for (int j = 0; j < 24; j++) {
            int dd = g + 8*j;
            float v = sY[dd*36 + li];
            v = (v - stat[li]) * stat[32 + li] * onw[dd] + onb[dd];
            float z = g_z[((b<<12) + l0 + li)*192 + dd];
            v *= z / (1.f + __expf(-z));
            sY[dd*36 + li] = v;
        }
    }
    __syncthreads();
    {   // out_proj GEMM: 96 out x 32 px, depth 192
        float a0[4] = {0,0,0,0}, a1[4] = {0,0,0,0}, a2[4] = {0,0,0,0};
        const float* w0p = &sW[lane*193];
        const float* w1p = &sW[(lane+32)*193];
        const float* w2p = &sW[(lane+64)*193];
        #pragma unroll 4
        for (int dd = 0; dd < 192; dd++) {
            float4 xv = *(const float4*)&sY[dd*36 + p0];
            float wv0 = w0p[dd], wv1 = w1p[dd], wv2 = w2p[dd];
            a0[0] = fmaf(wv0, xv.x, a0[0]); a0[1] = fmaf(wv0, xv.y, a0[1]);
            a0[2] = fmaf(wv0, xv.z, a0[2]); a0[3] = fmaf(wv0, xv.w, a0[3]);
            a1[0] = fmaf(wv1, xv.x, a1[0]); a1[1] = fmaf(wv1, xv.y, a1[1]);
            a1[2] = fmaf(wv1, xv.z, a1[2]); a1[3] = fmaf(wv1, xv.w, a1[3]);
            a2[0] = fmaf(wv2, xv.x, a2[0]); a2[1] = fmaf(wv2, xv.y, a2[1]);
            a2[2] = fmaf(wv2, xv.z, a2[2]); a2[3] = fmaf(wv2, xv.w, a2[3]);
        }
        #pragma unroll
        for (int p = 0; p < 4; p++) {
            sO[lane*36      + p0 + p] = a0[p];
            sO[(lane+32)*36 + p0 + p] = a1[p];
            sO[(lane+64)*36 + p0 + p] = a2[p];
        }
    }
    __syncthreads();
    for (int idx = tid; idx < 96*32; idx += 256) {
        int c = idx >> 5, li2 = idx & 31;
        int g = (b*96 + c)*4096 + l0 + li2;
        out[g] = sO[c*36 + li2] + xd[g] + xsh[g];
    }
}

extern "C" void kernel_launch(void* const* d_in, const int* in_sizes, int n_in,
                              void* d_out, int out_size) {
    const float* xd   = (const float*)d_in[0];
    const float* xsh  = (const float*)d_in[1];
    const float* w1   = (const float*)d_in[2];
    const float* b1   = (const float*)d_in[3];
    const float* ln1w = (const float*)d_in[4];
    const float* ln1b = (const float*)d_in[5];
    const float* w2   = (const float*)d_in[6];
    const float* b2   = (const float*)d_in[7];
    const float* ln2w = (const float*)d_in[8];
    const float* ln2b = (const float*)d_in[9];
    const float* nw   = (const float*)d_in[10];
    const float* nb   = (const float*)d_in[11];
    const float* wip  = (const float*)d_in[12];
    const float* cw   = (const float*)d_in[13];
    const float* cb   = (const float*)d_in[14];
    const float* xpw  = (const float*)d_in[15];
    const float* dtw  = (const float*)d_in[16];
    const float* dtb  = (const float*)d_in[17];
    const float* Alog = (const float*)d_in[18];
    const float* Ds   = (const float*)d_in[19];
    const float* onw  = (const float*)d_in[20];
    const float* onb  = (const float*)d_in[21];
    const float* opw  = (const float*)d_in[22];
    float* out = (float*)d_out;

    size_t smem_pre  = (9312u + 3456u + 3456u + 256u + 64u) * 4u;       // ~66 KB
    size_t smem_proj = 22950u * 4u;                                      // ~92 KB
    size_t smem_comb = (18528u + 6912u + 3456u + 256u + 64u) * 4u;       // ~117 KB
    cudaFuncSetAttribute(k_pre,  cudaFuncAttributeMaxDynamicSharedMemorySize, (int)smem_pre);
    cudaFuncSetAttribute(k_proj, cudaFuncAttributeMaxDynamicSharedMemorySize, (int)smem_proj);
    cudaFuncSetAttribute(k_comb, cudaFuncAttributeMaxDynamicSharedMemorySize, (int)smem_comb);

    k_pre<<<512, 256, smem_pre>>>(xd, xsh, w1, b1, ln1w, ln1b, w2, b2, ln2w, ln2b, nw, nb, wip);
    k_dw<<<12288, 256>>>(cw, cb);
    k_proj<<<2048, 256, smem_proj>>>(xpw, dtw, dtb);
    k_scan1<<<1024, 192>>>(Alog);
    k_scan_mid<<<192, 256>>>(Alog);
    k_scan2<<<1024, 192>>>(Alog, Ds);
    k_comb<<<512, 256, smem_comb>>>(xd, xsh, onw, onb, opw, out);
}

// round 8
// speedup vs baseline: 1.1313x; 1.1313x over previous
#include <cuda_runtime.h>
#include <math.h>

#define B_  4
#define L_  4096
#define D_  192
#define EPSF 1e-5f

typedef unsigned long long ull;

__device__ float g_xm[B_*L_*D_];
__device__ float g_z [B_*L_*D_];
__device__ float g_xc[B_*L_*D_];
__device__ float g_dt[16*L_*D_];
__device__ float g_Bs[16*L_*16];
__device__ float g_Cs[16*L_*16];
__device__ float g_ys[16*L_*D_];
__device__ float g_hloc[16*64*16*D_];
__device__ float g_hin [16*64*16*D_];
__device__ float g_Tc[16*64*D_];

__device__ __forceinline__ int map_l(int k, int l) {
    if (k == 0) return l;
    if (k == 1) return ((l & 63) << 6) | (l >> 6);
    if (k == 2) return 4095 - l;
    int r = 4095 - l;
    return ((r & 63) << 6) | (r >> 6);
}

__device__ __forceinline__ ull pk(float lo, float hi) {
    ull r; asm("mov.b64 %0, {%1, %2};" : "=l"(r) : "f"(lo), "f"(hi)); return r;
}
__device__ __forceinline__ void upk(ull v, float& lo, float& hi) {
    asm("mov.b64 {%0, %1}, %2;" : "=f"(lo), "=f"(hi) : "l"(v));
}
__device__ __forceinline__ ull ffma2(ull a, ull b, ull c) {
    ull d; asm("fma.rn.f32x2 %0, %1, %2, %3;" : "=l"(d) : "l"(a), "l"(b), "l"(c)); return d;
}
__device__ __forceinline__ ull mul2(ull a, ull b) {
    ull d; asm("mul.rn.f32x2 %0, %1, %2;" : "=l"(d) : "l"(a), "l"(b)); return d;
}

// ================= Kernel 1: pre-chain (R2 version) =================
__global__ void __launch_bounds__(256) k_pre(
    const float* __restrict__ xd, const float* __restrict__ xsh,
    const float* __restrict__ w1, const float* __restrict__ b1,
    const float* __restrict__ ln1w, const float* __restrict__ ln1b,
    const float* __restrict__ w2, const float* __restrict__ b2,
    const float* __restrict__ ln2w, const float* __restrict__ ln2b,
    const float* __restrict__ nw, const float* __restrict__ nb,
    const float* __restrict__ wip)
{
    extern __shared__ float sm[];
    float* sW   = sm;              // 96*98
    float* sA   = sW + 96*98;      // 96*33
    float* sB   = sA + 96*33;      // 96*33
    float* red  = sB + 96*33;      // 256
    float* stat = red + 256;       // 64

    const int tid = threadIdx.x;
    const int b  = blockIdx.x >> 7;
    const int l0 = (blockIdx.x & 127) << 5;

    auto loadW = [&](const float* W) {
        for (int idx = tid; idx < 96*96; idx += 256) {
            int o = idx / 96, c = idx % 96;
            sW[c*98 + o] = W[idx];
        }
    };

    auto gemm96 = [&](const float* in, float* out, const float* bias) {
        int og = tid >> 4, li = tid & 15, ob = og * 6;
        float a00=0,a01=0,a10=0,a11=0,a20=0,a21=0,a30=0,a31=0,a40=0,a41=0,a50=0,a51=0;
        #pragma unroll 4
        for (int c = 0; c < 96; c++) {
            float xa = in[c*33 + li];
            float xb = in[c*33 + li + 16];
            float2 w0 = *(const float2*)&sW[c*98 + ob];
            float2 wv1 = *(const float2*)&sW[c*98 + ob + 2];
            float2 wv2 = *(const float2*)&sW[c*98 + ob + 4];
            a00 = fmaf(w0.x, xa, a00);  a01 = fmaf(w0.x, xb, a01);
            a10 = fmaf(w0.y, xa, a10);  a11 = fmaf(w0.y, xb, a11);
            a20 = fmaf(wv1.x, xa, a20); a21 = fmaf(wv1.x, xb, a21);
            a30 = fmaf(wv1.y, xa, a30); a31 = fmaf(wv1.y, xb, a31);
            a40 = fmaf(wv2.x, xa, a40); a41 = fmaf(wv2.x, xb, a41);
            a50 = fmaf(wv2.y, xa, a50); a51 = fmaf(wv2.y, xb, a51);
        }
        float bv;
        bv = bias ? bias[ob+0] : 0.f; out[(ob+0)*33+li] = a00+bv; out[(ob+0)*33+li+16] = a01+bv;
        bv = bias ? bias[ob+1] : 0.f; out[(ob+1)*33+li] = a10+bv; out[(ob+1)*33+li+16] = a11+bv;
        bv = bias ? bias[ob+2] : 0.f; out[(ob+2)*33+li] = a20+bv; out[(ob+2)*33+li+16] = a21+bv;
        bv = bias ? bias[ob+3] : 0.f; out[(ob+3)*33+li] = a30+bv; out[(ob+3)*33+li+16] = a31+bv;
        bv = bias ? bias[ob+4] : 0.f; out[(ob+4)*33+li] = a40+bv; out[(ob+4)*33+li+16] = a41+bv;
        bv = bias ? bias[ob+5] : 0.f; out[(ob+5)*33+li] = a50+bv; out[(ob+5)*33+li+16] = a51+bv;
    };

    auto lnorm = [&](float* buf, const float* w, const float* bi, bool dogelu) {
        int g = tid >> 5, li = tid & 31;
        float p = 0.f;
        #pragma unroll
        for (int j = 0; j < 12; j++) p += buf[(g + 8*j)*33 + li];
        red[g*32 + li] = p;
        __syncthreads();
        if (tid < 32) {
            float s = 0.f;
            #pragma unroll
            for (int g2 = 0; g2 < 8; g2++) s += red[g2*32 + tid];
            stat[tid] = s * (1.f/96.f);
        }
        __syncthreads();
        float m = stat[li];
        p = 0.f;
        #pragma unroll
        for (int j = 0; j < 12; j++) { float v = buf[(g + 8*j)*33 + li] - m; p = fmaf(v, v, p); }
        red[g*32 + li] = p;
        __syncthreads();
        if (tid < 32) {
            float s = 0.f;
            #pragma unroll
            for (int g2 = 0; g2 < 8; g2++) s += red[g2*32 + tid];
            stat[32 + tid] = rsqrtf(s * (1.f/96.f) + EPSF);
        }
        __syncthreads();
        for (int idx = tid; idx < 96*32; idx += 256) {
            int li2 = idx / 96, o = idx % 96;
            float v = buf[o*33 + li2];
            v = (v - stat[li2]) * stat[32 + li2] * w[o] + bi[o];
            if (dogelu) v = 0.5f * v * (1.f + erff(v * 0.70710678118f));
            buf[o*33 + li2] = v;
        }
        __syncthreads();
    };

    for (int idx = tid; idx < 96*32; idx += 256) {
        int c = idx >> 5, li = idx & 31;
        int g = (b*96 + c)*4096 + l0 + li;
        sA[c*33 + li] = xd[g] + xsh[g];
    }
    loadW(w1);
    __syncthreads();
    gemm96(sA, sB, b1);
    __syncthreads();
    lnorm(sB, ln1w, ln1b, true);
    loadW(w2);
    __syncthreads();
    gemm96(sB, sA, b2);
    __syncthreads();
    lnorm(sA, ln2w, ln2b, false);
    lnorm(sA, nw, nb, false);
    for (int ch = 0; ch < 4; ch++) {
        loadW(wip + ch*96*96);
        __syncthreads();
        gemm96(sA, sB, nullptr);
        __syncthreads();
        float* dst = (ch < 2) ? g_xm : g_z;
        int dbase = (ch & 1) * 96;
        for (int idx = tid; idx < 96*32; idx += 256) {
            int li = idx / 96, dd = idx % 96;
            dst[(b*4096 + l0 + li)*192 + dbase + dd] = sB[dd*33 + li];
        }
        __syncthreads();
    }
}

// ================= Kernel 2: depthwise 3x3 + silu =================
__global__ void __launch_bounds__(256) k_dw(const float* __restrict__ cw, const float* __restrict__ cb)
{
    int idx = blockIdx.x * 256 + threadIdx.x;
    int d = idx % 192;
    int l = (idx / 192) & 4095;
    int b = idx / (192 * 4096);
    int h = l >> 6, w = l & 63;
    float acc = cb[d];
    #pragma unroll
    for (int dh = -1; dh <= 1; dh++) {
        int hh = h + dh;
        if ((unsigned)hh >= 64u) continue;
        #pragma unroll
        for (int dw = -1; dw <= 1; dw++) {
            int ww = w + dw;
            if ((unsigned)ww >= 64u) continue;
            acc = fmaf(g_xm[((b*4096) + (hh<<6) + ww)*192 + d],
                       cw[d*9 + (dh+1)*3 + (dw+1)], acc);
        }
    }
    g_xc[idx] = acc / (1.f + __expf(-acc));
}

// ================= Kernel 3: x_proj + dt proj + softplus (R2 version) =================
__global__ void __launch_bounds__(256) k_proj(
    const float* __restrict__ xpw, const float* __restrict__ dtw, const float* __restrict__ dtb)
{
    extern __shared__ float sm[];
    float* sX   = sm;               // 192*33
    float* sWp  = sX + 192*33;      // 192*40
    float* sDb  = sWp + 192*40;     // 38*33
    float* sdtw = sDb + 38*33;      // 1152
    float* sdtb = sdtw + 1152;      // 192
    float* sDt  = sdtb + 192;       // 192*33
    int tid = threadIdx.x;
    int bk = blockIdx.x >> 7;
    int tile = blockIdx.x & 127;
    int b = bk >> 2, k = bk & 3;
    int l0 = tile << 5;

    for (int idx = tid; idx < 192*32; idx += 256) {
        int li = idx / 192, d = idx % 192;
        int ml = map_l(k, l0 + li);
        sX[d*33 + li] = g_xc[(b*4096 + ml)*192 + d];
    }
    for (int idx = tid; idx < 38*192; idx += 256) {
        int c = idx / 192, d = idx % 192;
        sWp[d*40 + c] = xpw[(k*38 + c)*192 + d];
    }
    for (int idx = tid; idx < 1152; idx += 256) sdtw[idx] = dtw[k*1152 + idx];
    for (int idx = tid; idx < 192; idx += 256) sdtb[idx] = dtb[k*192 + idx];
    __syncthreads();
    {
        int og = tid >> 5, li = tid & 31;
        float acc[5] = {0.f,0.f,0.f,0.f,0.f};
        for (int d = 0; d < 192; d++) {
            float xv = sX[d*33 + li];
            #pragma unroll
            for (int j = 0; j < 5; j++) {
                int o = og + 8*j;
                if (o < 38) acc[j] = fmaf(sWp[d*40 + o], xv, acc[j]);
            }
        }
        #pragma unroll
        for (int j = 0; j < 5; j++) {
            int o = og + 8*j;
            if (o < 38) sDb[o*33 + li] = acc[j];
        }
    }
    __syncthreads();
    {
        int og = tid >> 5, li = tid & 31;
        float xr[6];
        #pragma unroll
        for (int r = 0; r < 6; r++) xr[r] = sDb[r*33 + li];
        #pragma unroll
        for (int j = 0; j < 24; j++) {
            int dd = og + 8*j;
            float acc = sdtb[dd];
            #pragma unroll
            for (int r = 0; r < 6; r++) acc = fmaf(xr[r], sdtw[dd*6 + r], acc);
            acc = (acc > 20.f) ? acc : log1pf(__expf(acc));
            sDt[dd*33 + li] = acc;
        }
    }
    __syncthreads();
    for (int idx = tid; idx < 192*32; idx += 256) {
        int li = idx / 192, dd = idx % 192;
        g_dt[((bk<<12) + l0 + li)*192 + dd] = sDt[dd*33 + li];
    }
    for (int idx = tid; idx < 32*16; idx += 256) {
        int li = idx >> 4, n = idx & 15;
        g_Bs[((bk<<12) + l0 + li)*16 + n] = sDb[(6 + n)*33 + li];
        g_Cs[((bk<<12) + l0 + li)*16 + n] = sDb[(22 + n)*33 + li];
    }
}

__device__ __forceinline__ void scan_maps(int k, int l0, int& ml0, int& mst) {
    if (k == 0)      { ml0 = l0;                          mst = 1;   }
    else if (k == 1) { ml0 = l0 >> 6;                     mst = 64;  }
    else if (k == 2) { ml0 = 4095 - l0;                   mst = -1;  }
    else             { ml0 = 4032 + 63 - (l0 >> 6);       mst = -64; }
}

// ================= Scan phase 1: chunk-local (192 thr, log-depth powers) =================
__global__ void __launch_bounds__(192) k_scan1(const float* __restrict__ Alogs)
{
    __shared__ float sB[1024];
    int d = threadIdx.x;
    int ch = blockIdx.x & 63;
    int bk = blockIdx.x >> 6;
    int b = bk >> 2, k = bk & 3;
    for (int idx = d; idx < 1024; idx += 192)
        sB[idx] = g_Bs[((bk<<12) + (ch<<6))*16 + idx];
    float Af[16]; bool stdA = true;
    #pragma unroll
    for (int n = 0; n < 16; n++) {
        Af[n] = -__expf(Alogs[(k*192 + d)*16 + n]);
        stdA = stdA && (fabsf(Af[n] + (float)(n+1)) < 1e-3f);
    }
    __syncthreads();
    int l0 = ch << 6;
    int ml0, mst;
    scan_maps(k, l0, ml0, mst);
    const float* dtp = g_dt + (((size_t)bk<<12) + l0)*192 + d;
    const float* xq  = g_xc + (((size_t)b<<12) + ml0)*192 + d;
    int xstep = mst * 192;
    float Ts = 0.f;
    int base = ((bk*64 + ch)*16)*192 + d;
    if (stdA) {
        ull H[8];
        #pragma unroll
        for (int i = 0; i < 8; i++) H[i] = 0;
        float dt_c = dtp[0], x_c = xq[0];
        #pragma unroll 2
        for (int s = 0; s < 64; s++) {
            float dt = dt_c, x = x_c;
            if (s < 63) { dt_c = dtp[(s+1)*192]; x_c = xq[(s+1)*xstep]; }
            float r = __expf(-dt);
            float dtx = dt * x;
            Ts += dt;
            float r2 = r * r;
            float r4 = r2 * r2;
            float r8 = r4 * r4;
            ull r2s = pk(r2, r2);
            ull r4s = pk(r4, r4);
            ull r8s = pk(r8, r8);
            ull dtxs = pk(dtx, dtx);
            const ull* Bp = (const ull*)(sB + s*16);
            // log-depth power pairs: P0=(r,r2) P1=P0*r2 P2=P0*r4 P3=P1*r4 P4..7 = P0..3*r8
            ull P0 = pk(r, r2);
            ull P1 = mul2(P0, r2s);
            ull P2 = mul2(P0, r4s);
            ull P3 = mul2(P1, r4s);
            H[0] = ffma2(P0, H[0], mul2(dtxs, Bp[0]));
            H[1] = ffma2(P1, H[1], mul2(dtxs, Bp[1]));
            H[2] = ffma2(P2, H[2], mul2(dtxs, Bp[2]));
            H[3] = ffma2(P3, H[3], mul2(dtxs, Bp[3]));
            H[4] = ffma2(mul2(P0, r8s), H[4], mul2(dtxs, Bp[4]));
            H[5] = ffma2(mul2(P1, r8s), H[5], mul2(dtxs, Bp[5]));
            H[6] = ffma2(mul2(P2, r8s), H[6], mul2(dtxs, Bp[6]));
            H[7] = ffma2(mul2(P3, r8s), H[7], mul2(dtxs, Bp[7]));
        }
        #pragma unroll
        for (int i = 0; i < 8; i++) {
            float v0, v1;
            upk(H[i], v0, v1);
            g_hloc[base + (2*i)*192]   = v0;
            g_hloc[base + (2*i+1)*192] = v1;
        }
    } else {
        float h[16];
        #pragma unroll
        for (int n = 0; n < 16; n++) h[n] = 0.f;
        for (int s = 0; s < 64; s++) {
            float dt = dtp[s*192];
            float x  = xq[s*xstep];
            float dtx = dt * x;
            Ts += dt;
            const float* Bp = &sB[s*16];
            #pragma unroll
            for (int n = 0; n < 16; n++)
                h[n] = fmaf(__expf(dt * Af[n]), h[n], dtx * Bp[n]);
        }
        #pragma unroll
        for (int n = 0; n < 16; n++) g_hloc[base + n*192] = h[n];
    }
    g_Tc[(bk*64 + ch)*192 + d] = Ts;
}

// ================= Scan phase 2: chunk prefix =================
__global__ void k_scan_mid(const float* __restrict__ Alogs)
{
    int gid = blockIdx.x * 256 + threadIdx.x;
    int d = gid % 192;
    int n = (gid / 192) & 15;
    int bk = gid / (192*16);
    int k = bk & 3;
    float An = -__expf(Alogs[(k*192 + d)*16 + n]);
    float h = 0.f;
    int idx = (bk*64*16 + n)*192 + d;
    int tcb = bk*64*192 + d;
    float Tc_c = g_Tc[tcb];
    float hl_c = g_hloc[idx];
    for (int ch = 0; ch < 64; ch++) {
        float Tc = Tc_c, hl = hl_c;
        if (ch < 63) {
            Tc_c = g_Tc[tcb + (ch+1)*192];
            hl_c = g_hloc[idx + (ch+1)*16*192];
        }
        g_hin[idx + ch*16*192] = h;
        h = fmaf(__expf(An * Tc), h, hl);
    }
}

// ================= Scan phase 3: rescan + y (192 thr, log-depth powers) =================
__global__ void __launch_bounds__(192) k_scan2(const float* __restrict__ Alogs, const float* __restrict__ Ds)
{
    __shared__ float sB[1024], sC[1024];
    int d = threadIdx.x;
    int ch = blockIdx.x & 63;
    int bk = blockIdx.x >> 6;
    int b = bk >> 2, k = bk & 3;
    for (int idx = d; idx < 1024; idx += 192) {
        sB[idx] = g_Bs[((bk<<12) + (ch<<6))*16 + idx];
        sC[idx] = g_Cs[((bk<<12) + (ch<<6))*16 + idx];
    }
    float Af[16]; bool stdA = true;
    #pragma unroll
    for (int n = 0; n < 16; n++) {
        Af[n] = -__expf(Alogs[(k*192 + d)*16 + n]);
        stdA = stdA && (fabsf(Af[n] + (float)(n+1)) < 1e-3f);
    }
    int base = ((bk*64 + ch)*16)*192 + d;
    float Dv = Ds[k*192 + d];
    __syncthreads();
    int l0 = ch << 6;
    int ml0, mst;
    scan_maps(k, l0, ml0, mst);
    const float* dtp = g_dt + (((size_t)bk<<12) + l0)*192 + d;
    const float* xq  = g_xc + (((size_t)b<<12) + ml0)*192 + d;
    int xstep = mst * 192;
    float* yp = g_ys + (((size_t)bk<<12) + l0)*192 + d;
    if (stdA) {
        ull H[8];
        #pragma unroll
        for (int i = 0; i < 8; i++)
            H[i] = pk(g_hin[base + (2*i)*192], g_hin[base + (2*i+1)*192]);
        float dt_c = dtp[0], x_c = xq[0];
        #pragma unroll 2
        for (int s = 0; s < 64; s++) {
            float dt = dt_c, x = x_c;
            if (s < 63) { dt_c = dtp[(s+1)*192]; x_c = xq[(s+1)*xstep]; }
            float r = __expf(-dt);
            float dtx = dt * x;
            float r2 = r * r;
            float r4 = r2 * r2;
            float r8 = r4 * r4;
            ull r2s = pk(r2, r2);
            ull r4s = pk(r4, r4);
            ull r8s = pk(r8, r8);
            ull dtxs = pk(dtx, dtx);
            ull Y = pk(Dv * x, 0.f);
            const ull* Bp = (const ull*)(sB + s*16);
            const ull* Cp = (const ull*)(sC + s*16);
            ull P0 = pk(r, r2);
            ull P1 = mul2(P0, r2s);
            ull P2 = mul2(P0, r4s);
            ull P3 = mul2(P1, r4s);
            H[0] = ffma2(P0, H[0], mul2(dtxs, Bp[0])); Y = ffma2(H[0], Cp[0], Y);
            H[1] = ffma2(P1, H[1], mul2(dtxs, Bp[1])); Y = ffma2(H[1], Cp[1], Y);
            H[2] = ffma2(P2, H[2], mul2(dtxs, Bp[2])); Y = ffma2(H[2], Cp[2], Y);
            H[3] = ffma2(P3, H[3], mul2(dtxs, Bp[3])); Y = ffma2(H[3], Cp[3], Y);
            H[4] = ffma2(mul2(P0, r8s), H[4], mul2(dtxs, Bp[4])); Y = ffma2(H[4], Cp[4], Y);
            H[5] = ffma2(mul2(P1, r8s), H[5], mul2(dtxs, Bp[5])); Y = ffma2(H[5], Cp[5], Y);
            H[6] = ffma2(mul2(P2, r8s), H[6], mul2(dtxs, Bp[6])); Y = ffma2(H[6], Cp[6], Y);
            H[7] = ffma2(mul2(P3, r8s), H[7], mul2(dtxs, Bp[7])); Y = ffma2(H[7], Cp[7], Y);
            float y0, y1;
            upk(Y, y0, y1);
            yp[s*192] = y0 + y1;
        }
    } else {
        float h[16];
        #pragma unroll
        for (int n = 0; n < 16; n++) h[n] = g_hin[base + n*192];
        for (int s = 0; s < 64; s++) {
            float dt = dtp[s*192];
            float x  = xq[s*xstep];
            float dtx = dt * x;
            float y = Dv * x;
            const float* Bp = &sB[s*16];
            const float* Cp = &sC[s*16];
            #pragma unroll
            for (int n = 0; n < 16; n++) {
                h[n] = fmaf(__expf(dt * Af[n]), h[n], dtx * Bp[n]);
                y = fmaf(h[n], Cp[n], y);
            }
            yp[s*192] = y;
        }
    }
}

// ================= Kernel 7: combine (R2 version) =================
__global__ void __launch_bounds__(256) k_comb(
    const float* __restrict__ xd, const float* __restrict__ xsh,
    const float* __restrict__ onw, const float* __restrict__ onb,
    const float* __restrict__ opw, float* __restrict__ out)
{
    extern __shared__ float sm[];
    float* sW   = sm;              // 192*98
    float* sY   = sW + 192*98;     // 192*33
    float* sO   = sY + 192*33;     // 96*33
    float* red  = sO + 96*33;      // 256
    float* stat = red + 256;       // 64
    int tid = threadIdx.x;
    int b = blockIdx.x >> 7;
    int l0 = (blockIdx.x & 127) << 5;

    for (int idx = tid; idx < 96*192; idx += 256) {
        int c = idx / 192, dd = idx % 192;
        sW[dd*98 + c] = opw[idx];
    }
    for (int idx = tid; idx < 192*32; idx += 256) {
        int li = idx / 192, dd = idx % 192;
        int p = l0 + li;
        float acc = 0.f;
        #pragma unroll
        for (int k = 0; k < 4; k++) {
            int s = map_l(k, p);
            acc += g_ys[(((b*4 + k)<<12) + s)*192 + dd];
        }
        sY[dd*33 + li] = acc;
    }
    __syncthreads();
    {
        int g = tid >> 5, li = tid & 31;
        float p = 0.f;
        #pragma unroll
        for (int j = 0; j < 24; j++) p += sY[(g + 8*j)*33 + li];
        red[g*32 + li] = p;
        __syncthreads();
        if (tid < 32) {
            float s = 0.f;
            #pragma unroll
            for (int g2 = 0; g2 < 8; g2++) s += red[g2*32 + tid];
            stat[tid] = s * (1.f/192.f);
        }
        __syncthreads();
        float m = stat[li];
        p = 0.f;
        #pragma unroll
        for (int j = 0; j < 24; j++) { float v = sY[(g + 8*j)*33 + li] - m; p = fmaf(v, v, p); }
        red[g*32 + li] = p;
        __syncthreads();
        if (tid < 32) {
            float s = 0.f;
            #pragma unroll
            for (int g2 = 0; g2 < 8; g2++) s += red[g2*32 + tid];
            stat[32 + tid] = rsqrtf(s * (1.f/192.f) + EPSF);
        }
        __syncthreads();
    }
    for (int idx = tid; idx < 192*32; idx += 256) {
        int li2 = idx / 192, dd = idx % 192;
        float v = sY[dd*33 + li2];
        v = (v - stat[li2]) * stat[32 + li2] * onw[dd] + onb[dd];
        float z = g_z[((b<<12) + l0 + li2)*192 + dd];
        v *= z / (1.f + __expf(-z));
        sY[dd*33 + li2] = v;
    }
    __syncthreads();
    {
        int og = tid >> 4, li = tid & 15, ob = og * 6;
        float a00=0,a01=0,a10=0,a11=0,a20=0,a21=0,a30=0,a31=0,a40=0,a41=0,a50=0,a51=0;
        #pragma unroll 4
        for (int dd = 0; dd < 192; dd++) {
            float xa = sY[dd*33 + li];
            float xb = sY[dd*33 + li + 16];
            float2 w0 = *(const float2*)&sW[dd*98 + ob];
            float2 wv1 = *(const float2*)&sW[dd*98 + ob + 2];
            float2 wv2 = *(const float2*)&sW[dd*98 + ob + 4];
            a00 = fmaf(w0.x, xa, a00);  a01 = fmaf(w0.x, xb, a01);
            a10 = fmaf(w0.y, xa, a10);  a11 = fmaf(w0.y, xb, a11);
            a20 = fmaf(wv1.x, xa, a20); a21 = fmaf(wv1.x, xb, a21);
            a30 = fmaf(wv1.y, xa, a30); a31 = fmaf(wv1.y, xb, a31);
            a40 = fmaf(wv2.x, xa, a40); a41 = fmaf(wv2.x, xb, a41);
            a50 = fmaf(wv2.y, xa, a50); a51 = fmaf(wv2.y, xb, a51);
        }
        sO[(ob+0)*33+li] = a00; sO[(ob+0)*33+li+16] = a01;
        sO[(ob+1)*33+li] = a10; sO[(ob+1)*33+li+16] = a11;
        sO[(ob+2)*33+li] = a20; sO[(ob+2)*33+li+16] = a21;
        sO[(ob+3)*33+li] = a30; sO[(ob+3)*33+li+16] = a31;
        sO[(ob+4)*33+li] = a40; sO[(ob+4)*33+li+16] = a41;
        sO[(ob+5)*33+li] = a50; sO[(ob+5)*33+li+16] = a51;
    }
    __syncthreads();
    for (int idx = tid; idx < 96*32; idx += 256) {
        int c = idx >> 5, li2 = idx & 31;
        int g = (b*96 + c)*4096 + l0 + li2;
        out[g] = sO[c*33 + li2] + xd[g] + xsh[g];
    }
}

extern "C" void kernel_launch(void* const* d_in, const int* in_sizes, int n_in,
                              void* d_out, int out_size) {
    const float* xd   = (const float*)d_in[0];
    const float* xsh  = (const float*)d_in[1];
    const float* w1   = (const float*)d_in[2];
    const float* b1   = (const float*)d_in[3];
    const float* ln1w = (const float*)d_in[4];
    const float* ln1b = (const float*)d_in[5];
    const float* w2   = (const float*)d_in[6];
    const float* b2   = (const float*)d_in[7];
    const float* ln2w = (const float*)d_in[8];
    const float* ln2b = (const float*)d_in[9];
    const float* nw   = (const float*)d_in[10];
    const float* nb   = (const float*)d_in[11];
    const float* wip  = (const float*)d_in[12];
    const float* cw   = (const float*)d_in[13];
    const float* cb   = (const float*)d_in[14];
    const float* xpw  = (const float*)d_in[15];
    const float* dtw  = (const float*)d_in[16];
    const float* dtb  = (const float*)d_in[17];
    const float* Alog = (const float*)d_in[18];
    const float* Ds   = (const float*)d_in[19];
    const float* onw  = (const float*)d_in[20];
    const float* onb  = (const float*)d_in[21];
    const float* opw  = (const float*)d_in[22];
    float* out = (float*)d_out;

    size_t smem_pre  = 16064u * 4u;
    size_t smem_proj = 22950u * 4u;
    size_t smem_comb = 28640u * 4u;
    cudaFuncSetAttribute(k_pre,  cudaFuncAttributeMaxDynamicSharedMemorySize, (int)smem_pre);
    cudaFuncSetAttribute(k_proj, cudaFuncAttributeMaxDynamicSharedMemorySize, (int)smem_proj);
    cudaFuncSetAttribute(k_comb, cudaFuncAttributeMaxDynamicSharedMemorySize, (int)smem_comb);

    k_pre<<<512, 256, smem_pre>>>(xd, xsh, w1, b1, ln1w, ln1b, w2, b2, ln2w, ln2b, nw, nb, wip);
    k_dw<<<12288, 256>>>(cw, cb);
    k_proj<<<2048, 256, smem_proj>>>(xpw, dtw, dtb);
    k_scan1<<<1024, 192>>>(Alog);
    k_scan_mid<<<192, 256>>>(Alog);
    k_scan2<<<1024, 192>>>(Alog, Ds);
    k_comb<<<512, 256, smem_comb>>>(xd, xsh, onw, onb, opw, out);
}

// round 9
// speedup vs baseline: 1.1745x; 1.0381x over previous
#include <cuda_runtime.h>
#include <math.h>

#define B_  4
#define L_  4096
#define D_  192
#define EPSF 1e-5f
#define NCH 128          // chunks per (b,k)
#define CSZ 32           // steps per chunk

typedef unsigned long long ull;

__device__ float g_xm[B_*L_*D_];
__device__ float g_z [B_*L_*D_];
__device__ float g_xc[B_*L_*D_];
__device__ float g_dt[16*L_*D_];
__device__ float g_Bs[16*L_*16];
__device__ float g_Cs[16*L_*16];
__device__ float g_ys[16*L_*D_];
__device__ float g_hloc[16*NCH*16*D_];
__device__ float g_hin [16*NCH*16*D_];
__device__ float g_Tc[16*NCH*D_];

__device__ __forceinline__ int map_l(int k, int l) {
    if (k == 0) return l;
    if (k == 1) return ((l & 63) << 6) | (l >> 6);
    if (k == 2) return 4095 - l;
    int r = 4095 - l;
    return ((r & 63) << 6) | (r >> 6);
}

__device__ __forceinline__ ull pk(float lo, float hi) {
    ull r; asm("mov.b64 %0, {%1, %2};" : "=l"(r) : "f"(lo), "f"(hi)); return r;
}
__device__ __forceinline__ void upk(ull v, float& lo, float& hi) {
    asm("mov.b64 {%0, %1}, %2;" : "=f"(lo), "=f"(hi) : "l"(v));
}
__device__ __forceinline__ ull ffma2(ull a, ull b, ull c) {
    ull d; asm("fma.rn.f32x2 %0, %1, %2, %3;" : "=l"(d) : "l"(a), "l"(b), "l"(c)); return d;
}
__device__ __forceinline__ ull mul2(ull a, ull b) {
    ull d; asm("mul.rn.f32x2 %0, %1, %2;" : "=l"(d) : "l"(a), "l"(b)); return d;
}

// ================= Kernel 1: pre-chain (R2 version) =================
__global__ void __launch_bounds__(256) k_pre(
    const float* __restrict__ xd, const float* __restrict__ xsh,
    const float* __restrict__ w1, const float* __restrict__ b1,
    const float* __restrict__ ln1w, const float* __restrict__ ln1b,
    const float* __restrict__ w2, const float* __restrict__ b2,
    const float* __restrict__ ln2w, const float* __restrict__ ln2b,
    const float* __restrict__ nw, const float* __restrict__ nb,
    const float* __restrict__ wip)
{
    extern __shared__ float sm[];
    float* sW   = sm;              // 96*98
    float* sA   = sW + 96*98;      // 96*33
    float* sB   = sA + 96*33;      // 96*33
    float* red  = sB + 96*33;      // 256
    float* stat = red + 256;       // 64

    const int tid = threadIdx.x;
    const int b  = blockIdx.x >> 7;
    const int l0 = (blockIdx.x & 127) << 5;

    auto loadW = [&](const float* W) {
        for (int idx = tid; idx < 96*96; idx += 256) {
            int o = idx / 96, c = idx % 96;
            sW[c*98 + o] = W[idx];
        }
    };

    auto gemm96 = [&](const float* in, float* out, const float* bias) {
        int og = tid >> 4, li = tid & 15, ob = og * 6;
        float a00=0,a01=0,a10=0,a11=0,a20=0,a21=0,a30=0,a31=0,a40=0,a41=0,a50=0,a51=0;
        #pragma unroll 4
        for (int c = 0; c < 96; c++) {
            float xa = in[c*33 + li];
            float xb = in[c*33 + li + 16];
            float2 w0 = *(const float2*)&sW[c*98 + ob];
            float2 wv1 = *(const float2*)&sW[c*98 + ob + 2];
            float2 wv2 = *(const float2*)&sW[c*98 + ob + 4];
            a00 = fmaf(w0.x, xa, a00);  a01 = fmaf(w0.x, xb, a01);
            a10 = fmaf(w0.y, xa, a10);  a11 = fmaf(w0.y, xb, a11);
            a20 = fmaf(wv1.x, xa, a20); a21 = fmaf(wv1.x, xb, a21);
            a30 = fmaf(wv1.y, xa, a30); a31 = fmaf(wv1.y, xb, a31);
            a40 = fmaf(wv2.x, xa, a40); a41 = fmaf(wv2.x, xb, a41);
            a50 = fmaf(wv2.y, xa, a50); a51 = fmaf(wv2.y, xb, a51);
        }
        float bv;
        bv = bias ? bias[ob+0] : 0.f; out[(ob+0)*33+li] = a00+bv; out[(ob+0)*33+li+16] = a01+bv;
        bv = bias ? bias[ob+1] : 0.f; out[(ob+1)*33+li] = a10+bv; out[(ob+1)*33+li+16] = a11+bv;
        bv = bias ? bias[ob+2] : 0.f; out[(ob+2)*33+li] = a20+bv; out[(ob+2)*33+li+16] = a21+bv;
        bv = bias ? bias[ob+3] : 0.f; out[(ob+3)*33+li] = a30+bv; out[(ob+3)*33+li+16] = a31+bv;
        bv = bias ? bias[ob+4] : 0.f; out[(ob+4)*33+li] = a40+bv; out[(ob+4)*33+li+16] = a41+bv;
        bv = bias ? bias[ob+5] : 0.f; out[(ob+5)*33+li] = a50+bv; out[(ob+5)*33+li+16] = a51+bv;
    };

    auto lnorm = [&](float* buf, const float* w, const float* bi, bool dogelu) {
        int g = tid >> 5, li = tid & 31;
        float p = 0.f;
        #pragma unroll
        for (int j = 0; j < 12; j++) p += buf[(g + 8*j)*33 + li];
        red[g*32 + li] = p;
        __syncthreads();
        if (tid < 32) {
            float s = 0.f;
            #pragma unroll
            for (int g2 = 0; g2 < 8; g2++) s += red[g2*32 + tid];
            stat[tid] = s * (1.f/96.f);
        }
        __syncthreads();
        float m = stat[li];
        p = 0.f;
        #pragma unroll
        for (int j = 0; j < 12; j++) { float v = buf[(g + 8*j)*33 + li] - m; p = fmaf(v, v, p); }
        red[g*32 + li] = p;
        __syncthreads();
        if (tid < 32) {
            float s = 0.f;
            #pragma unroll
            for (int g2 = 0; g2 < 8; g2++) s += red[g2*32 + tid];
            stat[32 + tid] = rsqrtf(s * (1.f/96.f) + EPSF);
        }
        __syncthreads();
        for (int idx = tid; idx < 96*32; idx += 256) {
            int li2 = idx / 96, o = idx % 96;
            float v = buf[o*33 + li2];
            v = (v - stat[li2]) * stat[32 + li2] * w[o] + bi[o];
            if (dogelu) v = 0.5f * v * (1.f + erff(v * 0.70710678118f));
            buf[o*33 + li2] = v;
        }
        __syncthreads();
    };

    for (int idx = tid; idx < 96*32; idx += 256) {
        int c = idx >> 5, li = idx & 31;
        int g = (b*96 + c)*4096 + l0 + li;
        sA[c*33 + li] = xd[g] + xsh[g];
    }
    loadW(w1);
    __syncthreads();
    gemm96(sA, sB, b1);
    __syncthreads();
    lnorm(sB, ln1w, ln1b, true);
    loadW(w2);
    __syncthreads();
    gemm96(sB, sA, b2);
    __syncthreads();
    lnorm(sA, ln2w, ln2b, false);
    lnorm(sA, nw, nb, false);
    for (int ch = 0; ch < 4; ch++) {
        loadW(wip + ch*96*96);
        __syncthreads();
        gemm96(sA, sB, nullptr);
        __syncthreads();
        float* dst = (ch < 2) ? g_xm : g_z;
        int dbase = (ch & 1) * 96;
        for (int idx = tid; idx < 96*32; idx += 256) {
            int li = idx / 96, dd = idx % 96;
            dst[(b*4096 + l0 + li)*192 + dbase + dd] = sB[dd*33 + li];
        }
        __syncthreads();
    }
}

// ================= Kernel 2: depthwise 3x3 + silu =================
__global__ void __launch_bounds__(256) k_dw(const float* __restrict__ cw, const float* __restrict__ cb)
{
    int idx = blockIdx.x * 256 + threadIdx.x;
    int d = idx % 192;
    int l = (idx / 192) & 4095;
    int b = idx / (192 * 4096);
    int h = l >> 6, w = l & 63;
    float acc = cb[d];
    #pragma unroll
    for (int dh = -1; dh <= 1; dh++) {
        int hh = h + dh;
        if ((unsigned)hh >= 64u) continue;
        #pragma unroll
        for (int dw = -1; dw <= 1; dw++) {
            int ww = w + dw;
            if ((unsigned)ww >= 64u) continue;
            acc = fmaf(g_xm[((b*4096) + (hh<<6) + ww)*192 + d],
                       cw[d*9 + (dh+1)*3 + (dw+1)], acc);
        }
    }
    g_xc[idx] = acc / (1.f + __expf(-acc));
}

// ================= Kernel 3: x_proj + dt proj + softplus (sDt aliased onto sWp) =================
__global__ void __launch_bounds__(256) k_proj(
    const float* __restrict__ xpw, const float* __restrict__ dtw, const float* __restrict__ dtb)
{
    extern __shared__ float sm[];
    float* sX   = sm;               // 192*33 = 6336
    float* sWp  = sX + 6336;        // 192*40 = 7680 (reused as sDt after GEMM1)
    float* sDt  = sWp;              // alias (6336 <= 7680)
    float* sDb  = sWp + 7680;       // 38*33 = 1254
    float* sdtw = sDb + 1254;       // 1152
    float* sdtb = sdtw + 1152;      // 192
    int tid = threadIdx.x;
    int bk = blockIdx.x >> 7;
    int tile = blockIdx.x & 127;
    int b = bk >> 2, k = bk & 3;
    int l0 = tile << 5;

    for (int idx = tid; idx < 192*32; idx += 256) {
        int li = idx / 192, d = idx % 192;
        int ml = map_l(k, l0 + li);
        sX[d*33 + li] = g_xc[(b*4096 + ml)*192 + d];
    }
    for (int idx = tid; idx < 38*192; idx += 256) {
        int c = idx / 192, d = idx % 192;
        sWp[d*40 + c] = xpw[(k*38 + c)*192 + d];
    }
    for (int idx = tid; idx < 1152; idx += 256) sdtw[idx] = dtw[k*1152 + idx];
    for (int idx = tid; idx < 192; idx += 256) sdtb[idx] = dtb[k*192 + idx];
    __syncthreads();
    {
        int og = tid >> 5, li = tid & 31;
        float acc[5] = {0.f,0.f,0.f,0.f,0.f};
        for (int d = 0; d < 192; d++) {
            float xv = sX[d*33 + li];
            #pragma unroll
            for (int j = 0; j < 5; j++) {
                int o = og + 8*j;
                if (o < 38) acc[j] = fmaf(sWp[d*40 + o], xv, acc[j]);
            }
        }
        __syncthreads();   // GEMM1 done before sDt (=sWp) is overwritten
        #pragma unroll
        for (int j = 0; j < 5; j++) {
            int o = og + 8*j;
            if (o < 38) sDb[o*33 + li] = acc[j];
        }
    }
    __syncthreads();
    {
        int og = tid >> 5, li = tid & 31;
        float xr[6];
        #pragma unroll
        for (int r = 0; r < 6; r++) xr[r] = sDb[r*33 + li];
        #pragma unroll
        for (int j = 0; j < 24; j++) {
            int dd = og + 8*j;
            float acc = sdtb[dd];
            #pragma unroll
            for (int r = 0; r < 6; r++) acc = fmaf(xr[r], sdtw[dd*6 + r], acc);
            acc = (acc > 20.f) ? acc : log1pf(__expf(acc));
            sDt[dd*33 + li] = acc;
        }
    }
    __syncthreads();
    for (int idx = tid; idx < 192*32; idx += 256) {
        int li = idx / 192, dd = idx % 192;
        g_dt[((bk<<12) + l0 + li)*192 + dd] = sDt[dd*33 + li];
    }
    for (int idx = tid; idx < 32*16; idx += 256) {
        int li = idx >> 4, n = idx & 15;
        g_Bs[((bk<<12) + l0 + li)*16 + n] = sDb[(6 + n)*33 + li];
        g_Cs[((bk<<12) + l0 + li)*16 + n] = sDb[(22 + n)*33 + li];
    }
}

// general l0 (multiple of 32) direction map: ml = ml0 + s*mst for s in [0,CSZ)
__device__ __forceinline__ void scan_maps(int k, int l0, int& ml0, int& mst) {
    if (k == 0)      { ml0 = l0;                                     mst = 1;   }
    else if (k == 1) { ml0 = ((l0 & 63) << 6) | (l0 >> 6);           mst = 64;  }
    else if (k == 2) { ml0 = 4095 - l0;                              mst = -1;  }
    else             { ml0 = ((63 - (l0 & 63)) << 6) | (63 - (l0 >> 6)); mst = -64; }
}

// ================= Scan phase 1: chunk-local (128 chunks x 32 steps) =================
__global__ void __launch_bounds__(192) k_scan1(const float* __restrict__ Alogs)
{
    __shared__ float sB[CSZ*16];
    int d = threadIdx.x;
    int ch = blockIdx.x & (NCH-1);
    int bk = blockIdx.x >> 7;
    int b = bk >> 2, k = bk & 3;
    int l0 = ch * CSZ;
    for (int idx = d; idx < CSZ*16; idx += 192)
        sB[idx] = g_Bs[((bk<<12) + l0)*16 + idx];
    float Af[16]; bool stdA = true;
    #pragma unroll
    for (int n = 0; n < 16; n++) {
        Af[n] = -__expf(Alogs[(k*192 + d)*16 + n]);
        stdA = stdA && (fabsf(Af[n] + (float)(n+1)) < 1e-3f);
    }
    __syncthreads();
    int ml0, mst;
    scan_maps(k, l0, ml0, mst);
    const float* dtp = g_dt + (((size_t)bk<<12) + l0)*192 + d;
    const float* xq  = g_xc + (((size_t)b<<12) + ml0)*192 + d;
    int xstep = mst * 192;
    float Ts = 0.f;
    int base = ((bk*NCH + ch)*16)*192 + d;
    if (stdA) {
        ull H[8];
        #pragma unroll
        for (int i = 0; i < 8; i++) H[i] = 0;
        float dt_c = dtp[0], x_c = xq[0];
        #pragma unroll 2
        for (int s = 0; s < CSZ; s++) {
            float dt = dt_c, x = x_c;
            if (s < CSZ-1) { dt_c = dtp[(s+1)*192]; x_c = xq[(s+1)*xstep]; }
            float r = __expf(-dt);
            float dtx = dt * x;
            Ts += dt;
            float r2 = r * r;
            float r4 = r2 * r2;
            float r8 = r4 * r4;
            ull r2s = pk(r2, r2);
            ull r4s = pk(r4, r4);
            ull r8s = pk(r8, r8);
            ull dtxs = pk(dtx, dtx);
            const ull* Bp = (const ull*)(sB + s*16);
            ull P0 = pk(r, r2);
            ull P1 = mul2(P0, r2s);
            ull P2 = mul2(P0, r4s);
            ull P3 = mul2(P1, r4s);
            H[0] = ffma2(P0, H[0], mul2(dtxs, Bp[0]));
            H[1] = ffma2(P1, H[1], mul2(dtxs, Bp[1]));
            H[2] = ffma2(P2, H[2], mul2(dtxs, Bp[2]));
            H[3] = ffma2(P3, H[3], mul2(dtxs, Bp[3]));
            H[4] = ffma2(mul2(P0, r8s), H[4], mul2(dtxs, Bp[4]));
            H[5] = ffma2(mul2(P1, r8s), H[5], mul2(dtxs, Bp[5]));
            H[6] = ffma2(mul2(P2, r8s), H[6], mul2(dtxs, Bp[6]));
            H[7] = ffma2(mul2(P3, r8s), H[7], mul2(dtxs, Bp[7]));
        }
        #pragma unroll
        for (int i = 0; i < 8; i++) {
            float v0, v1;
            upk(H[i], v0, v1);
            g_hloc[base + (2*i)*192]   = v0;
            g_hloc[base + (2*i+1)*192] = v1;
        }
    } else {
        float h[16];
        #pragma unroll
        for (int n = 0; n < 16; n++) h[n] = 0.f;
        for (int s = 0; s < CSZ; s++) {
            float dt = dtp[s*192];
            float x  = xq[s*xstep];
            float dtx = dt * x;
            Ts += dt;
            const float* Bp = &sB[s*16];
            #pragma unroll
            for (int n = 0; n < 16; n++)
                h[n] = fmaf(__expf(dt * Af[n]), h[n], dtx * Bp[n]);
        }
        #pragma unroll
        for (int n = 0; n < 16; n++) g_hloc[base + n*192] = h[n];
    }
    g_Tc[(bk*NCH + ch)*192 + d] = Ts;
}

// ================= Scan phase 2: chunk prefix =================
__global__ void k_scan_mid(const float* __restrict__ Alogs)
{
    int gid = blockIdx.x * 256 + threadIdx.x;
    int d = gid % 192;
    int n = (gid / 192) & 15;
    int bk = gid / (192*16);
    int k = bk & 3;
    float An = -__expf(Alogs[(k*192 + d)*16 + n]);
    float h = 0.f;
    int idx = (bk*NCH*16 + n)*192 + d;
    int tcb = bk*NCH*192 + d;
    float Tc_c = g_Tc[tcb];
    float hl_c = g_hloc[idx];
    for (int ch = 0; ch < NCH; ch++) {
        float Tc = Tc_c, hl = hl_c;
        if (ch < NCH-1) {
            Tc_c = g_Tc[tcb + (ch+1)*192];
            hl_c = g_hloc[idx + (ch+1)*16*192];
        }
        g_hin[idx + ch*16*192] = h;
        h = fmaf(__expf(An * Tc), h, hl);
    }
}

// ================= Scan phase 3: rescan + y =================
__global__ void __launch_bounds__(192) k_scan2(const float* __restrict__ Alogs, const float* __restrict__ Ds)
{
    __shared__ float sB[CSZ*16], sC[CSZ*16];
    int d = threadIdx.x;
    int ch = blockIdx.x & (NCH-1);
    int bk = blockIdx.x >> 7;
    int b = bk >> 2, k = bk & 3;
    int l0 = ch * CSZ;
    for (int idx = d; idx < CSZ*16; idx += 192) {
        sB[idx] = g_Bs[((bk<<12) + l0)*16 + idx];
        sC[idx] = g_Cs[((bk<<12) + l0)*16 + idx];
    }
    float Af[16]; bool stdA = true;
    #pragma unroll
    for (int n = 0; n < 16; n++) {
        Af[n] = -__expf(Alogs[(k*192 + d)*16 + n]);
        stdA = stdA && (fabsf(Af[n] + (float)(n+1)) < 1e-3f);
    }
    int base = ((bk*NCH + ch)*16)*192 + d;
    float Dv = Ds[k*192 + d];
    __syncthreads();
    int ml0, mst;
    scan_maps(k, l0, ml0, mst);
    const float* dtp = g_dt + (((size_t)bk<<12) + l0)*192 + d;
    const float* xq  = g_xc + (((size_t)b<<12) + ml0)*192 + d;
    int xstep = mst * 192;
    float* yp = g_ys + (((size_t)bk<<12) + l0)*192 + d;
    if (stdA) {
        ull H[8];
        #pragma unroll
        for (int i = 0; i < 8; i++)
            H[i] = pk(g_hin[base + (2*i)*192], g_hin[base + (2*i+1)*192]);
        float dt_c = dtp[0], x_c = xq[0];
        #pragma unroll 2
        for (int s = 0; s < CSZ; s++) {
            float dt = dt_c, x = x_c;
            if (s < CSZ-1) { dt_c = dtp[(s+1)*192]; x_c = xq[(s+1)*xstep]; }
            float r = __expf(-dt);
            float dtx = dt * x;
            float r2 = r * r;
            float r4 = r2 * r2;
            float r8 = r4 * r4;
            ull r2s = pk(r2, r2);
            ull r4s = pk(r4, r4);
            ull r8s = pk(r8, r8);
            ull dtxs = pk(dtx, dtx);
            ull Y = pk(Dv * x, 0.f);
            const ull* Bp = (const ull*)(sB + s*16);
            const ull* Cp = (const ull*)(sC + s*16);
            ull P0 = pk(r, r2);
            ull P1 = mul2(P0, r2s);
            ull P2 = mul2(P0, r4s);
            ull P3 = mul2(P1, r4s);
            H[0] = ffma2(P0, H[0], mul2(dtxs, Bp[0])); Y = ffma2(H[0], Cp[0], Y);
            H[1] = ffma2(P1, H[1], mul2(dtxs, Bp[1])); Y = ffma2(H[1], Cp[1], Y);
            H[2] = ffma2(P2, H[2], mul2(dtxs, Bp[2])); Y = ffma2(H[2], Cp[2], Y);
            H[3] = ffma2(P3, H[3], mul2(dtxs, Bp[3])); Y = ffma2(H[3], Cp[3], Y);
            H[4] = ffma2(mul2(P0, r8s), H[4], mul2(dtxs, Bp[4])); Y = ffma2(H[4], Cp[4], Y);
            H[5] = ffma2(mul2(P1, r8s), H[5], mul2(dtxs, Bp[5])); Y = ffma2(H[5], Cp[5], Y);
            H[6] = ffma2(mul2(P2, r8s), H[6], mul2(dtxs, Bp[6])); Y = ffma2(H[6], Cp[6], Y);
            H[7] = ffma2(mul2(P3, r8s), H[7], mul2(dtxs, Bp[7])); Y = ffma2(H[7], Cp[7], Y);
            float y0, y1;
            upk(Y, y0, y1);
            yp[s*192] = y0 + y1;
        }
    } else {
        float h[16];
        #pragma unroll
        for (int n = 0; n < 16; n++) h[n] = g_hin[base + n*192];
        for (int s = 0; s < CSZ; s++) {
            float dt = dtp[s*192];
            float x  = xq[s*xstep];
            float dtx = dt * x;
            float y = Dv * x;
            const float* Bp = &sB[s*16];
            const float* Cp = &sC[s*16];
            #pragma unroll
            for (int n = 0; n < 16; n++) {
                h[n] = fmaf(__expf(dt * Af[n]), h[n], dtx * Bp[n]);
                y = fmaf(h[n], Cp[n], y);
            }
            yp[s*192] = y;
        }
    }
}

// ================= Kernel 7: combine (red/stat aliased onto sO) =================
__global__ void __launch_bounds__(256) k_comb(
    const float* __restrict__ xd, const float* __restrict__ xsh,
    const float* __restrict__ onw, const float* __restrict__ onb,
    const float* __restrict__ opw, float* __restrict__ out)
{
    extern __shared__ float sm[];
    float* sW   = sm;              // 192*98 = 18816
    float* sY   = sW + 18816;      // 192*33 = 6336
    float* sO   = sY + 6336;       // 96*33 = 3168 (first 320 reused as red/stat during LN)
    float* red  = sO;              // alias: LN scratch, dead before sO is written
    float* stat = sO + 256;        // alias
    int tid = threadIdx.x;
    int b = blockIdx.x >> 7;
    int l0 = (blockIdx.x & 127) << 5;

    for (int idx = tid; idx < 96*192; idx += 256) {
        int c = idx / 192, dd = idx % 192;
        sW[dd*98 + c] = opw[idx];
    }
    for (int idx = tid; idx < 192*32; idx += 256) {
        int li = idx / 192, dd = idx % 192;
        int p = l0 + li;
        float acc = 0.f;
        #pragma unroll
        for (int k = 0; k < 4; k++) {
            int s = map_l(k, p);
            acc += g_ys[(((b*4 + k)<<12) + s)*192 + dd];
        }
        sY[dd*33 + li] = acc;
    }
    __syncthreads();
    {
        int g = tid >> 5, li = tid & 31;
        float p = 0.f;
        #pragma unroll
        for (int j = 0; j < 24; j++) p += sY[(g + 8*j)*33 + li];
        red[g*32 + li] = p;
        __syncthreads();
        if (tid < 32) {
            float s = 0.f;
            #pragma unroll
            for (int g2 = 0; g2 < 8; g2++) s += red[g2*32 + tid];
            stat[tid] = s * (1.f/192.f);
        }
        __syncthreads();
        float m = stat[li];
        p = 0.f;
        #pragma unroll
        for (int j = 0; j < 24; j++) { float v = sY[(g + 8*j)*33 + li] - m; p = fmaf(v, v, p); }
        red[g*32 + li] = p;
        __syncthreads();
        if (tid < 32) {
            float s = 0.f;
            #pragma unroll
            for (int g2 = 0; g2 < 8; g2++) s += red[g2*32 + tid];
            stat[32 + tid] = rsqrtf(s * (1.f/192.f) + EPSF);
        }
        __syncthreads();
    }
    for (int idx = tid; idx < 192*32; idx += 256) {
        int li2 = idx / 192, dd = idx % 192;
        float v = sY[dd*33 + li2];
        v = (v - stat[li2]) * stat[32 + li2] * onw[dd] + onb[dd];
        float z = g_z[((b<<12) + l0 + li2)*192 + dd];
        v *= z / (1.f + __expf(-z));
        sY[dd*33 + li2] = v;
    }
    __syncthreads();
    {
        int og = tid >> 4, li = tid & 15, ob = og * 6;
        float a00=0,a01=0,a10=0,a11=0,a20=0,a21=0,a30=0,a31=0,a40=0,a41=0,a50=0,a51=0;
        #pragma unroll 4
        for (int dd = 0; dd < 192; dd++) {
            float xa = sY[dd*33 + li];
            float xb = sY[dd*33 + li + 16];
            float2 w0 = *(const float2*)&sW[dd*98 + ob];
            float2 wv1 = *(const float2*)&sW[dd*98 + ob + 2];
            float2 wv2 = *(const float2*)&sW[dd*98 + ob + 4];
            a00 = fmaf(w0.x, xa, a00);  a01 = fmaf(w0.x, xb, a01);
            a10 = fmaf(w0.y, xa, a10);  a11 = fmaf(w0.y, xb, a11);
            a20 = fmaf(wv1.x, xa, a20); a21 = fmaf(wv1.x, xb, a21);
            a30 = fmaf(wv1.y, xa, a30); a31 = fmaf(wv1.y, xb, a31);
            a40 = fmaf(wv2.x, xa, a40); a41 = fmaf(wv2.x, xb, a41);
            a50 = fmaf(wv2.y, xa, a50); a51 = fmaf(wv2.y, xb, a51);
        }
        sO[(ob+0)*33+li] = a00; sO[(ob+0)*33+li+16] = a01;
        sO[(ob+1)*33+li] = a10; sO[(ob+1)*33+li+16] = a11;
        sO[(ob+2)*33+li] = a20; sO[(ob+2)*33+li+16] = a21;
        sO[(ob+3)*33+li] = a30; sO[(ob+3)*33+li+16] = a31;
        sO[(ob+4)*33+li] = a40; sO[(ob+4)*33+li+16] = a41;
        sO[(ob+5)*33+li] = a50; sO[(ob+5)*33+li+16] = a51;
    }
    __syncthreads();
    for (int idx = tid; idx < 96*32; idx += 256) {
        int c = idx >> 5, li2 = idx & 31;
        int g = (b*96 + c)*4096 + l0 + li2;
        out[g] = sO[c*33 + li2] + xd[g] + xsh[g];
    }
}

extern "C" void kernel_launch(void* const* d_in, const int* in_sizes, int n_in,
                              void* d_out, int out_size) {
    const float* xd   = (const float*)d_in[0];
    const float* xsh  = (const float*)d_in[1];
    const float* w1   = (const float*)d_in[2];
    const float* b1   = (const float*)d_in[3];
    const float* ln1w = (const float*)d_in[4];
    const float* ln1b = (const float*)d_in[5];
    const float* w2   = (const float*)d_in[6];
    const float* b2   = (const float*)d_in[7];
    const float* ln2w = (const float*)d_in[8];
    const float* ln2b = (const float*)d_in[9];
    const float* nw   = (const float*)d_in[10];
    const float* nb   = (const float*)d_in[11];
    const float* wip  = (const float*)d_in[12];
    const float* cw   = (const float*)d_in[13];
    const float* cb   = (const float*)d_in[14];
    const float* xpw  = (const float*)d_in[15];
    const float* dtw  = (const float*)d_in[16];
    const float* dtb  = (const float*)d_in[17];
    const float* Alog = (const float*)d_in[18];
    const float* Ds   = (const float*)d_in[19];
    const float* onw  = (const float*)d_in[20];
    const float* onb  = (const float*)d_in[21];
    const float* opw  = (const float*)d_in[22];
    float* out = (float*)d_out;

    size_t smem_pre  = 16064u * 4u;   // 64.3 KB -> 3 blocks/SM
    size_t smem_proj = 16614u * 4u;   // 66.5 KB -> 3 blocks/SM
    size_t smem_comb = 28320u * 4u;   // 113.3 KB -> 2 blocks/SM
    cudaFuncSetAttribute(k_pre,  cudaFuncAttributeMaxDynamicSharedMemorySize, (int)smem_pre);
    cudaFuncSetAttribute(k_proj, cudaFuncAttributeMaxDynamicSharedMemorySize, (int)smem_proj);
    cudaFuncSetAttribute(k_comb, cudaFuncAttributeMaxDynamicSharedMemorySize, (int)smem_comb);

    k_pre<<<512, 256, smem_pre>>>(xd, xsh, w1, b1, ln1w, ln1b, w2, b2, ln2w, ln2b, nw, nb, wip);
    k_dw<<<12288, 256>>>(cw, cb);
    k_proj<<<2048, 256, smem_proj>>>(xpw, dtw, dtb);
    k_scan1<<<16*NCH, 192>>>(Alog);
    k_scan_mid<<<192, 256>>>(Alog);
    k_scan2<<<16*NCH, 192>>>(Alog, Ds);
    k_comb<<<512, 256, smem_comb>>>(xd, xsh, onw, onb, opw, out);
}

// round 10
// speedup vs baseline: 1.1937x; 1.0164x over previous
#include <cuda_runtime.h>
#include <math.h>

#define B_  4
#define L_  4096
#define D_  192
#define EPSF 1e-5f
#define NCH 128          // chunks per (b,k)
#define CSZ 32           // steps per chunk

typedef unsigned long long ull;

__device__ float g_xm[B_*L_*D_];
__device__ float g_z [B_*L_*D_];
__device__ float g_xc[B_*L_*D_];
__device__ float g_dt[16*L_*D_];
__device__ float g_Bs[16*L_*16];
__device__ float g_Cs[16*L_*16];
__device__ float g_ys[16*L_*D_];
__device__ float g_hloc[16*NCH*16*D_];
__device__ float g_hin [16*NCH*16*D_];
__device__ float g_Tc[16*NCH*D_];

__device__ __forceinline__ int map_l(int k, int l) {
    if (k == 0) return l;
    if (k == 1) return ((l & 63) << 6) | (l >> 6);
    if (k == 2) return 4095 - l;
    int r = 4095 - l;
    return ((r & 63) << 6) | (r >> 6);
}

__device__ __forceinline__ ull pk(float lo, float hi) {
    ull r; asm("mov.b64 %0, {%1, %2};" : "=l"(r) : "f"(lo), "f"(hi)); return r;
}
__device__ __forceinline__ void upk(ull v, float& lo, float& hi) {
    asm("mov.b64 {%0, %1}, %2;" : "=f"(lo), "=f"(hi) : "l"(v));
}
__device__ __forceinline__ ull ffma2(ull a, ull b, ull c) {
    ull d; asm("fma.rn.f32x2 %0, %1, %2, %3;" : "=l"(d) : "l"(a), "l"(b), "l"(c)); return d;
}
__device__ __forceinline__ ull mul2(ull a, ull b) {
    ull d; asm("mul.rn.f32x2 %0, %1, %2;" : "=l"(d) : "l"(a), "l"(b)); return d;
}

// ================= Kernel 1: pre-chain (f32x2 GEMM, stride-98 weights) =================
__global__ void __launch_bounds__(256) k_pre(
    const float* __restrict__ xd, const float* __restrict__ xsh,
    const float* __restrict__ w1, const float* __restrict__ b1,
    const float* __restrict__ ln1w, const float* __restrict__ ln1b,
    const float* __restrict__ w2, const float* __restrict__ b2,
    const float* __restrict__ ln2w, const float* __restrict__ ln2b,
    const float* __restrict__ nw, const float* __restrict__ nb,
    const float* __restrict__ wip)
{
    extern __shared__ float sm[];
    float* sW   = sm;              // 96*98
    float* sA   = sW + 96*98;      // 96*33
    float* sB   = sA + 96*33;      // 96*33
    float* red  = sB + 96*33;      // 256
    float* stat = red + 256;       // 64

    const int tid = threadIdx.x;
    const int b  = blockIdx.x >> 7;
    const int l0 = (blockIdx.x & 127) << 5;

    auto loadW = [&](const float* W) {
        for (int idx = tid; idx < 96*96; idx += 256) {
            int o = idx / 96, c = idx % 96;
            sW[c*98 + o] = W[idx];       // stride 98: 2-way conflict max, ull-aligned at even o
        }
    };

    auto gemm96 = [&](const float* in, float* out, const float* bias) {
        int og = tid >> 4, li = tid & 15, ob = og * 6;
        ull A0=0,A1=0,A2=0,A3=0,A4=0,A5=0;
        #pragma unroll 4
        for (int c = 0; c < 96; c++) {
            float xa = in[c*33 + li];
            float xb = in[c*33 + li + 16];
            ull xpa = pk(xa, xa), xpb = pk(xb, xb);
            const ull* wr = (const ull*)&sW[c*98 + ob];
            ull w01 = wr[0], w23 = wr[1], w45 = wr[2];
            A0 = ffma2(w01, xpa, A0);  A1 = ffma2(w01, xpb, A1);
            A2 = ffma2(w23, xpa, A2);  A3 = ffma2(w23, xpb, A3);
            A4 = ffma2(w45, xpa, A4);  A5 = ffma2(w45, xpb, A5);
        }
        float v0, v1;
        float b0 = bias ? bias[ob+0] : 0.f;
        float b1v = bias ? bias[ob+1] : 0.f;
        float b2v = bias ? bias[ob+2] : 0.f;
        float b3 = bias ? bias[ob+3] : 0.f;
        float b4 = bias ? bias[ob+4] : 0.f;
        float b5 = bias ? bias[ob+5] : 0.f;
        upk(A0, v0, v1); out[(ob+0)*33+li]    = v0+b0;  out[(ob+1)*33+li]    = v1+b1v;
        upk(A1, v0, v1); out[(ob+0)*33+li+16] = v0+b0;  out[(ob+1)*33+li+16] = v1+b1v;
        upk(A2, v0, v1); out[(ob+2)*33+li]    = v0+b2v; out[(ob+3)*33+li]    = v1+b3;
        upk(A3, v0, v1); out[(ob+2)*33+li+16] = v0+b2v; out[(ob+3)*33+li+16] = v1+b3;
        upk(A4, v0, v1); out[(ob+4)*33+li]    = v0+b4;  out[(ob+5)*33+li]    = v1+b5;
        upk(A5, v0, v1); out[(ob+4)*33+li+16] = v0+b4;  out[(ob+5)*33+li+16] = v1+b5;
    };

    auto lnorm = [&](float* buf, const float* w, const float* bi, bool dogelu) {
        int g = tid >> 5, li = tid & 31;
        float p = 0.f;
        #pragma unroll
        for (int j = 0; j < 12; j++) p += buf[(g + 8*j)*33 + li];
        red[g*32 + li] = p;
        __syncthreads();
        if (tid < 32) {
            float s = 0.f;
            #pragma unroll
            for (int g2 = 0; g2 < 8; g2++) s += red[g2*32 + tid];
            stat[tid] = s * (1.f/96.f);
        }
        __syncthreads();
        float m = stat[li];
        p = 0.f;
        #pragma unroll
        for (int j = 0; j < 12; j++) { float v = buf[(g + 8*j)*33 + li] - m; p = fmaf(v, v, p); }
        red[g*32 + li] = p;
        __syncthreads();
        if (tid < 32) {
            float s = 0.f;
            #pragma unroll
            for (int g2 = 0; g2 < 8; g2++) s += red[g2*32 + tid];
            stat[32 + tid] = rsqrtf(s * (1.f/96.f) + EPSF);
        }
        __syncthreads();
        for (int idx = tid; idx < 96*32; idx += 256) {
            int li2 = idx / 96, o = idx % 96;
            float v = buf[o*33 + li2];
            v = (v - stat[li2]) * stat[32 + li2] * w[o] + bi[o];
            if (dogelu) v = 0.5f * v * (1.f + erff(v * 0.70710678118f));
            buf[o*33 + li2] = v;
        }
        __syncthreads();
    };

    for (int idx = tid; idx < 96*32; idx += 256) {
        int c = idx >> 5, li = idx & 31;
        int g = (b*96 + c)*4096 + l0 + li;
        sA[c*33 + li] = xd[g] + xsh[g];
    }
    loadW(w1);
    __syncthreads();
    gemm96(sA, sB, b1);
    __syncthreads();
    lnorm(sB, ln1w, ln1b, true);
    loadW(w2);
    __syncthreads();
    gemm96(sB, sA, b2);
    __syncthreads();
    lnorm(sA, ln2w, ln2b, false);
    lnorm(sA, nw, nb, false);
    for (int ch = 0; ch < 4; ch++) {
        loadW(wip + ch*96*96);
        __syncthreads();
        gemm96(sA, sB, nullptr);
        __syncthreads();
        float* dst = (ch < 2) ? g_xm : g_z;
        int dbase = (ch & 1) * 96;
        for (int idx = tid; idx < 96*32; idx += 256) {
            int li = idx / 96, dd = idx % 96;
            dst[(b*4096 + l0 + li)*192 + dbase + dd] = sB[dd*33 + li];
        }
        __syncthreads();
    }
}

// ================= Kernel 2: depthwise 3x3 + silu =================
__global__ void __launch_bounds__(256) k_dw(const float* __restrict__ cw, const float* __restrict__ cb)
{
    int idx = blockIdx.x * 256 + threadIdx.x;
    int d = idx % 192;
    int l = (idx / 192) & 4095;
    int b = idx / (192 * 4096);
    int h = l >> 6, w = l & 63;
    float acc = cb[d];
    #pragma unroll
    for (int dh = -1; dh <= 1; dh++) {
        int hh = h + dh;
        if ((unsigned)hh >= 64u) continue;
        #pragma unroll
        for (int dw = -1; dw <= 1; dw++) {
            int ww = w + dw;
            if ((unsigned)ww >= 64u) continue;
            acc = fmaf(g_xm[((b*4096) + (hh<<6) + ww)*192 + d],
                       cw[d*9 + (dh+1)*3 + (dw+1)], acc);
        }
    }
    g_xc[idx] = acc / (1.f + __expf(-acc));
}

// ================= Kernel 3: x_proj + dt proj (f32x2, 48-padded), sDt aliased on sWp =================
__global__ void __launch_bounds__(256) k_proj(
    const float* __restrict__ xpw, const float* __restrict__ dtw, const float* __restrict__ dtb)
{
    extern __shared__ float sm[];
    float* sX    = sm;               // 192*33 = 6336
    float* sWp   = sX + 6336;        // 192*48 = 9216 (reused as sDt after GEMM1)
    float* sDt   = sWp;              // alias (6336 <= 9216)
    float* sDb   = sWp + 9216;       // 38*33 = 1254
    float* sdtwT = sDb + 1254;       // 6*192 = 1152
    float* sdtb  = sdtwT + 1152;     // 192
    int tid = threadIdx.x;
    int bk = blockIdx.x >> 7;
    int tile = blockIdx.x & 127;
    int b = bk >> 2, k = bk & 3;
    int l0 = tile << 5;

    for (int idx = tid; idx < 192*32; idx += 256) {
        int li = idx / 192, d = idx % 192;
        int ml = map_l(k, l0 + li);
        sX[d*33 + li] = g_xc[(b*4096 + ml)*192 + d];
    }
    for (int idx = tid; idx < 192*10; idx += 256) {   // zero pad cols 38..47
        int d = idx / 10, c = 38 + idx % 10;
        sWp[d*48 + c] = 0.f;
    }
    for (int idx = tid; idx < 38*192; idx += 256) {
        int c = idx / 192, d = idx % 192;
        sWp[d*48 + c] = xpw[(k*38 + c)*192 + d];
    }
    for (int idx = tid; idx < 1152; idx += 256) {
        int d = idx / 6, r = idx % 6;
        sdtwT[r*192 + d] = dtw[k*1152 + idx];
    }
    for (int idx = tid; idx < 192; idx += 256) sdtb[idx] = dtb[k*192 + idx];
    __syncthreads();
    {   // GEMM1: 48 padded outputs (38 real) x 32 pixels, depth 192, f32x2
        int og = tid >> 5, li = tid & 31, ob = og * 6;
        ull A0=0, A1=0, A2=0;
        #pragma unroll 4
        for (int d = 0; d < 192; d++) {
            float xv = sX[d*33 + li];
            ull xp = pk(xv, xv);
            const ull* wr = (const ull*)&sWp[d*48 + ob];
            A0 = ffma2(wr[0], xp, A0);
            A1 = ffma2(wr[1], xp, A1);
            A2 = ffma2(wr[2], xp, A2);
        }
        __syncthreads();   // all sWp reads done before sDt (=sWp) is overwritten
        float v0, v1;
        upk(A0, v0, v1);
        if (ob+0 < 38) sDb[(ob+0)*33+li] = v0;
        if (ob+1 < 38) sDb[(ob+1)*33+li] = v1;
        upk(A1, v0, v1);
        if (ob+2 < 38) sDb[(ob+2)*33+li] = v0;
        if (ob+3 < 38) sDb[(ob+3)*33+li] = v1;
        upk(A2, v0, v1);
        if (ob+4 < 38) sDb[(ob+4)*33+li] = v0;
        if (ob+5 < 38) sDb[(ob+5)*33+li] = v1;
    }
    __syncthreads();
    {   // dt GEMM: 192 outputs x 32 pixels over R=6 + softplus, f32x2
        int og = tid >> 5, li = tid & 31;
        ull xrp[6];
        #pragma unroll
        for (int r = 0; r < 6; r++) { float xv = sDb[r*33 + li]; xrp[r] = pk(xv, xv); }
        #pragma unroll
        for (int j = 0; j < 12; j++) {
            int dd = og*24 + j*2;
            ull acc = pk(sdtb[dd], sdtb[dd+1]);
            #pragma unroll
            for (int r = 0; r < 6; r++)
                acc = ffma2(*(const ull*)&sdtwT[r*192 + dd], xrp[r], acc);
            float v0, v1;
            upk(acc, v0, v1);
            v0 = (v0 > 20.f) ? v0 : log1pf(__expf(v0));
            v1 = (v1 > 20.f) ? v1 : log1pf(__expf(v1));
            sDt[dd*33 + li] = v0;
            sDt[(dd+1)*33 + li] = v1;
        }
    }
    __syncthreads();
    for (int idx = tid; idx < 192*32; idx += 256) {
        int li = idx / 192, dd = idx % 192;
        g_dt[((bk<<12) + l0 + li)*192 + dd] = sDt[dd*33 + li];
    }
    for (int idx = tid; idx < 32*16; idx += 256) {
        int li = idx >> 4, n = idx & 15;
        g_Bs[((bk<<12) + l0 + li)*16 + n] = sDb[(6 + n)*33 + li];
        g_Cs[((bk<<12) + l0 + li)*16 + n] = sDb[(22 + n)*33 + li];
    }
}

// general l0 (multiple of 32) direction map
__device__ __forceinline__ void scan_maps(int k, int l0, int& ml0, int& mst) {
    if (k == 0)      { ml0 = l0;                                     mst = 1;   }
    else if (k == 1) { ml0 = ((l0 & 63) << 6) | (l0 >> 6);           mst = 64;  }
    else if (k == 2) { ml0 = 4095 - l0;                              mst = -1;  }
    else             { ml0 = ((63 - (l0 & 63)) << 6) | (63 - (l0 >> 6)); mst = -64; }
}

// ================= Scan phase 1: chunk-local =================
__global__ void __launch_bounds__(192) k_scan1(const float* __restrict__ Alogs)
{
    __shared__ float sB[CSZ*16];
    int d = threadIdx.x;
    int ch = blockIdx.x & (NCH-1);
    int bk = blockIdx.x >> 7;
    int b = bk >> 2, k = bk & 3;
    int l0 = ch * CSZ;
    for (int idx = d; idx < CSZ*16; idx += 192)
        sB[idx] = g_Bs[((bk<<12) + l0)*16 + idx];
    float Af[16]; bool stdA = true;
    #pragma unroll
    for (int n = 0; n < 16; n++) {
        Af[n] = -__expf(Alogs[(k*192 + d)*16 + n]);
        stdA = stdA && (fabsf(Af[n] + (float)(n+1)) < 1e-3f);
    }
    __syncthreads();
    int ml0, mst;
    scan_maps(k, l0, ml0, mst);
    const float* dtp = g_dt + (((size_t)bk<<12) + l0)*192 + d;
    const float* xq  = g_xc + (((size_t)b<<12) + ml0)*192 + d;
    int xstep = mst * 192;
    float Ts = 0.f;
    int base = ((bk*NCH + ch)*16)*192 + d;
    if (stdA) {
        ull H[8];
        #pragma unroll
        for (int i = 0; i < 8; i++) H[i] = 0;
        float dt_c = dtp[0], x_c = xq[0];
        #pragma unroll 2
        for (int s = 0; s < CSZ; s++) {
            float dt = dt_c, x = x_c;
            if (s < CSZ-1) { dt_c = dtp[(s+1)*192]; x_c = xq[(s+1)*xstep]; }
            float r = __expf(-dt);
            float dtx = dt * x;
            Ts += dt;
            float r2 = r * r;
            float r4 = r2 * r2;
            float r8 = r4 * r4;
            ull r2s = pk(r2, r2);
            ull r4s = pk(r4, r4);
            ull r8s = pk(r8, r8);
            ull dtxs = pk(dtx, dtx);
            const ull* Bp = (const ull*)(sB + s*16);
            ull P0 = pk(r, r2);
            ull P1 = mul2(P0, r2s);
            ull P2 = mul2(P0, r4s);
            ull P3 = mul2(P1, r4s);
            H[0] = ffma2(P0, H[0], mul2(dtxs, Bp[0]));
            H[1] = ffma2(P1, H[1], mul2(dtxs, Bp[1]));
            H[2] = ffma2(P2, H[2], mul2(dtxs, Bp[2]));
            H[3] = ffma2(P3, H[3], mul2(dtxs, Bp[3]));
            H[4] = ffma2(mul2(P0, r8s), H[4], mul2(dtxs, Bp[4]));
            H[5] = ffma2(mul2(P1, r8s), H[5], mul2(dtxs, Bp[5]));
            H[6] = ffma2(mul2(P2, r8s), H[6], mul2(dtxs, Bp[6]));
            H[7] = ffma2(mul2(P3, r8s), H[7], mul2(dtxs, Bp[7]));
        }
        #pragma unroll
        for (int i = 0; i < 8; i++) {
            float v0, v1;
            upk(H[i], v0, v1);
            g_hloc[base + (2*i)*192]   = v0;
            g_hloc[base + (2*i+1)*192] = v1;
        }
    } else {
        float h[16];
        #pragma unroll
        for (int n = 0; n < 16; n++) h[n] = 0.f;
        for (int s = 0; s < CSZ; s++) {
            float dt = dtp[s*192];
            float x  = xq[s*xstep];
            float dtx = dt * x;
            Ts += dt;
            const float* Bp = &sB[s*16];
            #pragma unroll
            for (int n = 0; n < 16; n++)
                h[n] = fmaf(__expf(dt * Af[n]), h[n], dtx * Bp[n]);
        }
        #pragma unroll
        for (int n = 0; n < 16; n++) g_hloc[base + n*192] = h[n];
    }
    g_Tc[(bk*NCH + ch)*192 + d] = Ts;
}

// ================= Scan phase 2: chunk prefix =================
__global__ void k_scan_mid(const float* __restrict__ Alogs)
{
    int gid = blockIdx.x * 256 + threadIdx.x;
    int d = gid % 192;
    int n = (gid / 192) & 15;
    int bk = gid / (192*16);
    int k = bk & 3;
    float An = -__expf(Alogs[(k*192 + d)*16 + n]);
    float h = 0.f;
    int idx = (bk*NCH*16 + n)*192 + d;
    int tcb = bk*NCH*192 + d;
    float Tc_c = g_Tc[tcb];
    float hl_c = g_hloc[idx];
    for (int ch = 0; ch < NCH; ch++) {
        float Tc = Tc_c, hl = hl_c;
        if (ch < NCH-1) {
            Tc_c = g_Tc[tcb + (ch+1)*192];
            hl_c = g_hloc[idx + (ch+1)*16*192];
        }
        g_hin[idx + ch*16*192] = h;
        h = fmaf(__expf(An * Tc), h, hl);
    }
}

// ================= Scan phase 3: rescan + y =================
__global__ void __launch_bounds__(192) k_scan2(const float* __restrict__ Alogs, const float* __restrict__ Ds)
{
    __shared__ float sB[CSZ*16], sC[CSZ*16];
    int d = threadIdx.x;
    int ch = blockIdx.x & (NCH-1);
    int bk = blockIdx.x >> 7;
    int b = bk >> 2, k = bk & 3;
    int l0 = ch * CSZ;
    for (int idx = d; idx < CSZ*16; idx += 192) {
        sB[idx] = g_Bs[((bk<<12) + l0)*16 + idx];
        sC[idx] = g_Cs[((bk<<12) + l0)*16 + idx];
    }
    float Af[16]; bool stdA = true;
    #pragma unroll
    for (int n = 0; n < 16; n++) {
        Af[n] = -__expf(Alogs[(k*192 + d)*16 + n]);
        stdA = stdA && (fabsf(Af[n] + (float)(n+1)) < 1e-3f);
    }
    int base = ((bk*NCH + ch)*16)*192 + d;
    float Dv = Ds[k*192 + d];
    __syncthreads();
    int ml0, mst;
    scan_maps(k, l0, ml0, mst);
    const float* dtp = g_dt + (((size_t)bk<<12) + l0)*192 + d;
    const float* xq  = g_xc + (((size_t)b<<12) + ml0)*192 + d;
    int xstep = mst * 192;
    float* yp = g_ys + (((size_t)bk<<12) + l0)*192 + d;
    if (stdA) {
        ull H[8];
        #pragma unroll
        for (int i = 0; i < 8; i++)
            H[i] = pk(g_hin[base + (2*i)*192], g_hin[base + (2*i+1)*192]);
        float dt_c = dtp[0], x_c = xq[0];
        #pragma unroll 2
        for (int s = 0; s < CSZ; s++) {
            float dt = dt_c, x = x_c;
            if (s < CSZ-1) { dt_c = dtp[(s+1)*192]; x_c = xq[(s+1)*xstep]; }
            float r = __expf(-dt);
            float dtx = dt * x;
            float r2 = r * r;
            float r4 = r2 * r2;
            float r8 = r4 * r4;
            ull r2s = pk(r2, r2);
            ull r4s = pk(r4, r4);
            ull r8s = pk(r8, r8);
            ull dtxs = pk(dtx, dtx);
            ull Y = pk(Dv * x, 0.f);
            const ull* Bp = (const ull*)(sB + s*16);
            const ull* Cp = (const ull*)(sC + s*16);
            ull P0 = pk(r, r2);
            ull P1 = mul2(P0, r2s);
            ull P2 = mul2(P0, r4s);
            ull P3 = mul2(P1, r4s);
            H[0] = ffma2(P0, H[0], mul2(dtxs, Bp[0])); Y = ffma2(H[0], Cp[0], Y);
            H[1] = ffma2(P1, H[1], mul2(dtxs, Bp[1])); Y = ffma2(H[1], Cp[1], Y);
            H[2] = ffma2(P2, H[2], mul2(dtxs, Bp[2])); Y = ffma2(H[2], Cp[2], Y);
            H[3] = ffma2(P3, H[3], mul2(dtxs, Bp[3])); Y = ffma2(H[3], Cp[3], Y);
            H[4] = ffma2(mul2(P0, r8s), H[4], mul2(dtxs, Bp[4])); Y = ffma2(H[4], Cp[4], Y);
            H[5] = ffma2(mul2(P1, r8s), H[5], mul2(dtxs, Bp[5])); Y = ffma2(H[5], Cp[5], Y);
            H[6] = ffma2(mul2(P2, r8s), H[6], mul2(dtxs, Bp[6])); Y = ffma2(H[6], Cp[6], Y);
            H[7] = ffma2(mul2(P3, r8s), H[7], mul2(dtxs, Bp[7])); Y = ffma2(H[7], Cp[7], Y);
            float y0, y1;
            upk(Y, y0, y1);
            yp[s*192] = y0 + y1;
        }
    } else {
        float h[16];
        #pragma unroll
        for (int n = 0; n < 16; n++) h[n] = g_hin[base + n*192];
        for (int s = 0; s < CSZ; s++) {
            float dt = dtp[s*192];
            float x  = xq[s*xstep];
            float dtx = dt * x;
            float y = Dv * x;
            const float* Bp = &sB[s*16];
            const float* Cp = &sC[s*16];
            #pragma unroll
            for (int n = 0; n < 16; n++) {
                h[n] = fmaf(__expf(dt * Af[n]), h[n], dtx * Bp[n]);
                y = fmaf(h[n], Cp[n], y);
            }
            yp[s*192] = y;
        }
    }
}

// ================= Kernel 7: combine (f32x2 out_proj, stride-98 weights, aliased scratch) =================
__global__ void __launch_bounds__(256) k_comb(
    const float* __restrict__ xd, const float* __restrict__ xsh,
    const float* __restrict__ onw, const float* __restrict__ onb,
    const float* __restrict__ opw, float* __restrict__ out)
{
    extern __shared__ float sm[];
    float* sW   = sm;              // 192*98 = 18816
    float* sY   = sW + 18816;      // 192*33 = 6336
    float* sO   = sY + 6336;       // 96*33 = 3168 (first 320 reused as red/stat during LN)
    float* red  = sO;              // alias
    float* stat = sO + 256;        // alias
    int tid = threadIdx.x;
    int b = blockIdx.x >> 7;
    int l0 = (blockIdx.x & 127) << 5;

    for (int idx = tid; idx < 96*192; idx += 256) {
        int c = idx / 192, dd = idx % 192;
        sW[dd*98 + c] = opw[idx];   // stride 98: consecutive dd -> 2-way max
    }
    for (int idx = tid; idx < 192*32; idx += 256) {
        int li = idx / 192, dd = idx % 192;
        int p = l0 + li;
        float acc = 0.f;
        #pragma unroll
        for (int k = 0; k < 4; k++) {
            int s = map_l(k, p);
            acc += g_ys[(((b*4 + k)<<12) + s)*192 + dd];
        }
        sY[dd*33 + li] = acc;
    }
    __syncthreads();
    {
        int g = tid >> 5, li = tid & 31;
        float p = 0.f;
        #pragma unroll
        for (int j = 0; j < 24; j++) p += sY[(g + 8*j)*33 + li];
        red[g*32 + li] = p;
        __syncthreads();
        if (tid < 32) {
            float s = 0.f;
            #pragma unroll
            for (int g2 = 0; g2 < 8; g2++) s += red[g2*32 + tid];
            stat[tid] = s * (1.f/192.f);
        }
        __syncthreads();
        float m = stat[li];
        p = 0.f;
        #pragma unroll
        for (int j = 0; j < 24; j++) { float v = sY[(g + 8*j)*33 + li] - m; p = fmaf(v, v, p); }
        red[g*32 + li] = p;
        __syncthreads();
        if (tid < 32) {
            float s = 0.f;
            #pragma unroll
            for (int g2 = 0; g2 < 8; g2++) s += red[g2*32 + tid];
            stat[32 + tid] = rsqrtf(s * (1.f/192.f) + EPSF);
        }
        __syncthreads();
    }
    for (int idx = tid; idx < 192*32; idx += 256) {
        int li2 = idx / 192, dd = idx % 192;
        float v = sY[dd*33 + li2];
        v = (v - stat[li2]) * stat[32 + li2] * onw[dd] + onb[dd];
        float z = g_z[((b<<12) + l0 + li2)*192 + dd];
        v *= z / (1.f + __expf(-z));
        sY[dd*33 + li2] = v;
    }
    __syncthreads();
    {
        int og = tid >> 4, li = tid & 15, ob = og * 6;
        ull A0=0,A1=0,A2=0,A3=0,A4=0,A5=0;
        #pragma unroll 4
        for (int dd = 0; dd < 192; dd++) {
            float xa = sY[dd*33 + li];
            float xb = sY[dd*33 + li + 16];
            ull xpa = pk(xa, xa), xpb = pk(xb, xb);
            const ull* wr = (const ull*)&sW[dd*98 + ob];
            ull w01 = wr[0], w23 = wr[1], w45 = wr[2];
            A0 = ffma2(w01, xpa, A0);  A1 = ffma2(w01, xpb, A1);
            A2 = ffma2(w23, xpa, A2);  A3 = ffma2(w23, xpb, A3);
            A4 = ffma2(w45, xpa, A4);  A5 = ffma2(w45, xpb, A5);
        }
        float v0, v1;
        upk(A0, v0, v1); sO[(ob+0)*33+li]    = v0; sO[(ob+1)*33+li]    = v1;
        upk(A1, v0, v1); sO[(ob+0)*33+li+16] = v0; sO[(ob+1)*33+li+16] = v1;
        upk(A2, v0, v1); sO[(ob+2)*33+li]    = v0; sO[(ob+3)*33+li]    = v1;
        upk(A3, v0, v1); sO[(ob+2)*33+li+16] = v0; sO[(ob+3)*33+li+16] = v1;
        upk(A4, v0, v1); sO[(ob+4)*33+li]    = v0; sO[(ob+5)*33+li]    = v1;
        upk(A5, v0, v1); sO[(ob+4)*33+li+16] = v0; sO[(ob+5)*33+li+16] = v1;
    }
    __syncthreads();
    for (int idx = tid; idx < 96*32; idx += 256) {
        int c = idx >> 5, li2 = idx & 31;
        int g = (b*96 + c)*4096 + l0 + li2;
        out[g] = sO[c*33 + li2] + xd[g] + xsh[g];
    }
}

extern "C" void kernel_launch(void* const* d_in, const int* in_sizes, int n_in,
                              void* d_out, int out_size) {
    const float* xd   = (const float*)d_in[0];
    const float* xsh  = (const float*)d_in[1];
    const float* w1   = (const float*)d_in[2];
    const float* b1   = (const float*)d_in[3];
    const float* ln1w = (const float*)d_in[4];
    const float* ln1b = (const float*)d_in[5];
    const float* w2   = (const float*)d_in[6];
    const float* b2   = (const float*)d_in[7];
    const float* ln2w = (const float*)d_in[8];
    const float* ln2b = (const float*)d_in[9];
    const float* nw   = (const float*)d_in[10];
    const float* nb   = (const float*)d_in[11];
    const float* wip  = (const float*)d_in[12];
    const float* cw   = (const float*)d_in[13];
    const float* cb   = (const float*)d_in[14];
    const float* xpw  = (const float*)d_in[15];
    const float* dtw  = (const float*)d_in[16];
    const float* dtb  = (const float*)d_in[17];
    const float* Alog = (const float*)d_in[18];
    const float* Ds   = (const float*)d_in[19];
    const float* onw  = (const float*)d_in[20];
    const float* onb  = (const float*)d_in[21];
    const float* opw  = (const float*)d_in[22];
    float* out = (float*)d_out;

    size_t smem_pre  = 16064u * 4u;   // 64.3 KB -> 3 blocks/SM
    size_t smem_proj = 18150u * 4u;   // 72.6 KB -> 3 blocks/SM
    size_t smem_comb = 28320u * 4u;   // 113.3 KB -> 2 blocks/SM
    cudaFuncSetAttribute(k_pre,  cudaFuncAttributeMaxDynamicSharedMemorySize, (int)smem_pre);
    cudaFuncSetAttribute(k_proj, cudaFuncAttributeMaxDynamicSharedMemorySize, (int)smem_proj);
    cudaFuncSetAttribute(k_comb, cudaFuncAttributeMaxDynamicSharedMemorySize, (int)smem_comb);

    k_pre<<<512, 256, smem_pre>>>(xd, xsh, w1, b1, ln1w, ln1b, w2, b2, ln2w, ln2b, nw, nb, wip);
    k_dw<<<12288, 256>>>(cw, cb);
    k_proj<<<2048, 256, smem_proj>>>(xpw, dtw, dtb);
    k_scan1<<<16*NCH, 192>>>(Alog);
    k_scan_mid<<<192, 256>>>(Alog);
    k_scan2<<<16*NCH, 192>>>(Alog, Ds);
    k_comb<<<512, 256, smem_comb>>>(xd, xsh, onw, onb, opw, out);
}